// round 12
// baseline (speedup 1.0000x reference)
#include <cuda_runtime.h>
#include <cuda_bf16.h>

#define BB 4
#define SS 1024
#define DDIM 768
#define HH 12
#define EE 8
#define HID 3072
#define DH 64
#define NTOK (BB*SS)
#define CAP (NTOK*2)

typedef __nv_bfloat16 bf16;
typedef __nv_bfloat162 bf162;

// ---------------- scratch ----------------
__device__ bf16  g_a[NTOK*DDIM];
__device__ bf16  g_q[NTOK*DDIM];
__device__ bf16  g_k[NTOK*DDIM];
__device__ bf16  g_v[NTOK*DDIM];
__device__ bf16  g_ctx[NTOK*DDIM];
__device__ float g_xa[NTOK*DDIM];
__device__ float g_h[NTOK*DDIM];
__device__ bf16  g_hr[NTOK*DDIM];
__device__ bf16  g_y1[CAP*HID];
__device__ float g_o2[CAP*DDIM];
__device__ float g_sc[CAP];
__device__ int   g_cnt[EE];
__device__ int   g_list[EE*CAP];
__device__ bf16  g_bwq[DDIM*DDIM];
__device__ bf16  g_bwk[DDIM*DDIM];
__device__ bf16  g_bwv[DDIM*DDIM];
__device__ bf16  g_bwo[DDIM*DDIM];
__device__ bf16  g_bw1[EE*DDIM*HID];
__device__ bf16  g_bw2[EE*HID*DDIM];

// ---------------- helpers ----------------
__device__ __forceinline__ unsigned smem_u32(const void* p) {
    return (unsigned)__cvta_generic_to_shared(p);
}
__device__ __forceinline__ void cp_async16(unsigned dst, const void* src, int srcsize) {
    asm volatile("cp.async.cg.shared.global [%0], [%1], 16, %2;"
                 :: "r"(dst), "l"(src), "r"(srcsize));
}
__device__ __forceinline__ void cp_commit() { asm volatile("cp.async.commit_group;"); }
template<int N>
__device__ __forceinline__ void cp_wait() { asm volatile("cp.async.wait_group %0;" :: "n"(N)); }

__device__ __forceinline__ void ldsm_x4(unsigned* r, unsigned addr) {
    asm volatile("ldmatrix.sync.aligned.m8n8.x4.shared.b16 {%0,%1,%2,%3}, [%4];"
        : "=r"(r[0]), "=r"(r[1]), "=r"(r[2]), "=r"(r[3]) : "r"(addr));
}
__device__ __forceinline__ void ldsm_x4_t(unsigned* r, unsigned addr) {
    asm volatile("ldmatrix.sync.aligned.m8n8.x4.trans.shared.b16 {%0,%1,%2,%3}, [%4];"
        : "=r"(r[0]), "=r"(r[1]), "=r"(r[2]), "=r"(r[3]) : "r"(addr));
}
__device__ __forceinline__ void mma_bf16(float c[4], const unsigned a[4],
                                         unsigned b0, unsigned b1) {
    asm volatile("mma.sync.aligned.m16n8k16.row.col.f32.bf16.bf16.f32 "
        "{%0,%1,%2,%3}, {%4,%5,%6,%7}, {%8,%9}, {%0,%1,%2,%3};"
        : "+f"(c[0]), "+f"(c[1]), "+f"(c[2]), "+f"(c[3])
        : "r"(a[0]), "r"(a[1]), "r"(a[2]), "r"(a[3]), "r"(b0), "r"(b1));
}
__device__ __forceinline__ unsigned pack_bf16(float a, float b) {
    bf162 t = __floats2bfloat162_rn(a, b);
    return *(unsigned*)&t;
}

__device__ __forceinline__ float blockReduceSum(float v) {
    __shared__ float sh[33];
    __syncthreads();
    int lane = threadIdx.x & 31, wid = threadIdx.x >> 5;
    #pragma unroll
    for (int o = 16; o > 0; o >>= 1) v += __shfl_down_sync(0xffffffffu, v, o);
    if (lane == 0) sh[wid] = v;
    __syncthreads();
    float r = (threadIdx.x < (blockDim.x >> 5)) ? sh[threadIdx.x] : 0.f;
    if (wid == 0) {
        #pragma unroll
        for (int o = 16; o > 0; o >>= 1) r += __shfl_down_sync(0xffffffffu, r, o);
        if (lane == 0) sh[32] = r;
    }
    __syncthreads();
    return sh[32];
}

// ---------------- weight conversion f32 -> bf16 ----------------
__global__ void conv_bf16_kernel(const float* __restrict__ src, bf16* __restrict__ dst, int n4) {
    int i = blockIdx.x * blockDim.x + threadIdx.x;
    if (i < n4) {
        float4 v = *(const float4*)(src + (size_t)i*4);
        bf162* d = (bf162*)(dst + (size_t)i*4);
        d[0] = __floats2bfloat162_rn(v.x, v.y);
        d[1] = __floats2bfloat162_rn(v.z, v.w);
    }
}

// ---------------- layernorm ----------------
template<int MODE>
__global__ void ln_kernel(const float* __restrict__ x, const float* __restrict__ g,
                          const float* __restrict__ b, float* __restrict__ out,
                          bf16* __restrict__ out_b) {
    int row = blockIdx.x;
    const float* xr = x + (size_t)row * DDIM;
    float v[3];
    float s = 0.f;
    #pragma unroll
    for (int i = 0; i < 3; i++) { v[i] = xr[threadIdx.x + i*256]; s += v[i]; }
    s = blockReduceSum(s);
    float mean = s * (1.f / DDIM);
    float vs = 0.f;
    #pragma unroll
    for (int i = 0; i < 3; i++) { float d = v[i] - mean; vs += d*d; }
    vs = blockReduceSum(vs);
    float rstd = rsqrtf(vs * (1.f / DDIM) + 1e-5f);
    #pragma unroll
    for (int i = 0; i < 3; i++) {
        int d = threadIdx.x + i*256;
        float y = (v[i] - mean) * rstd * g[d] + b[d];
        if (MODE == 1) out_b[(size_t)row*DDIM + d] = __float2bfloat16_rn(y);
        if (MODE == 2) {
            out  [(size_t)row*DDIM + d] = y;
            out_b[(size_t)row*DDIM + d] = __float2bfloat16_rn(y);
        }
    }
}

// ---------------- bf16 tensor-core GEMM: 256x128 CTA, 64x64 warp tile ----------------
// 8 warps (4 M x 2 N). BK=32, 4-stage cp.async pipeline.
// A smem: [256 rows][32 bf16] stride 40; B smem: [32 k][128 n] stride 136.
#define ABYT 20480   /* 256*40*2 */
#define BBYT 8704    /* 32*136*2 */
#define GSMEM (4*(ABYT + BBYT) + 1024)

template<bool GATHER, bool AROW_PAIR, bool RELU, bool RESID, bool OUTBF16, bool QKV3>
__global__ __launch_bounds__(256, 1) void bgemm_k(
    int M, int N, int K,
    const bf16* __restrict__ A, int lda,
    const bf16* __restrict__ Bm,
    const float* __restrict__ bias,
    const float* __restrict__ resid,
    float* __restrict__ C, int ldc,
    const int* __restrict__ rowlist,
    const int* __restrict__ cnt,
    const bf16* Bm2, const float* bias2, float* C2,
    const bf16* Bm3, const float* bias3, float* C3)
{
    extern __shared__ __align__(16) char smem_raw[];
    bf16* AsBase = (bf16*)smem_raw;                    // 4 * ABYT
    bf16* BsBase = (bf16*)(smem_raw + 4*ABYT);         // 4 * BBYT
    int*  rowsS  = (int*)(smem_raw + 4*(ABYT + BBYT)); // 256 ints

    if (QKV3) {
        int z = blockIdx.z;
        if (z == 1) { Bm = Bm2; bias = bias2; C = C2; }
        else if (z == 2) { Bm = Bm3; bias = bias3; C = C3; }
    }
    if (GATHER) {
        int e = blockIdx.z;
        Bm      += (size_t)e * K * N;
        bias    += (size_t)e * N;
        rowlist += (size_t)e * CAP;
        cnt     += e;
    }
    int m0 = blockIdx.y * 256, n0 = blockIdx.x * 128;
    int tid = threadIdx.x, lane = tid & 31, wid = tid >> 5;
    int warpM = wid & 3, warpN = wid >> 2;

    if (GATHER) {
        int Meff = *cnt;
        if (m0 >= Meff) return;
        int gidx = m0 + tid;
        rowsS[tid] = (gidx < Meff) ? rowlist[gidx] : -1;
        __syncthreads();
    }

    // ---- A staging: thread -> row tid, 4 chunks of 16B (32 bf16 / stage) ----
    const bf16* Aptr;
    int asz = 16;
    if (GATHER) {
        int pr = rowsS[tid];
        if (pr < 0) { Aptr = A; asz = 0; }
        else Aptr = A + (size_t)(AROW_PAIR ? pr : (pr >> 1)) * lda;
    } else {
        Aptr = A + (size_t)(m0 + tid) * lda;
    }
    unsigned aD0 = smem_u32(&AsBase[tid*40]);

    // ---- B staging: thread -> k-row tid>>3, 2 chunks at (tid&7)*16 elems ----
    int lbr = tid >> 3;
    int bce = (tid & 7) << 4;   // element offset within row
    const bf16* Bptr = Bm + (size_t)lbr * N + n0 + bce;
    unsigned bD0 = smem_u32(&BsBase[lbr*136 + bce]);

    // ---- ldmatrix addresses ----
    int lane8 = lane & 7, laneH = lane & 8, laneK = (lane & 16) >> 1;
    unsigned aAddr[4], bAddr[4];
    #pragma unroll
    for (int mt = 0; mt < 4; mt++) {
        int r = warpM*64 + mt*16 + lane8 + laneH;
        aAddr[mt] = smem_u32(&AsBase[r*40 + laneK]);
    }
    #pragma unroll
    for (int ntp = 0; ntp < 4; ntp++) {
        int kr = lane8 + laneH;
        int nc = warpN*64 + ntp*16 + laneK;
        bAddr[ntp] = smem_u32(&BsBase[kr*136 + nc]);
    }

    float acc[4][8][4];
    #pragma unroll
    for (int i = 0; i < 4; i++)
        #pragma unroll
        for (int j = 0; j < 8; j++)
            #pragma unroll
            for (int q = 0; q < 4; q++) acc[i][j][q] = 0.f;

    auto issueStage = [&](int k0, int buf) {
        unsigned ad = aD0 + buf*ABYT;
        const bf16* ap = Aptr + k0;
        #pragma unroll
        for (int j = 0; j < 4; j++) cp_async16(ad + j*16, ap + j*8, asz);
        unsigned bd = bD0 + buf*BBYT;
        const bf16* bp = Bptr + (size_t)k0 * N;
        cp_async16(bd,      bp,     16);
        cp_async16(bd + 16, bp + 8, 16);
        cp_commit();
    };

    int nStages = K >> 5;
    issueStage(0, 0);
    issueStage(32, 1);
    issueStage(64, 2);

    for (int s = 0; s < nStages; s++) {
        int rem = nStages - 1 - s;
        if (rem >= 2) cp_wait<2>();
        else if (rem == 1) cp_wait<1>();
        else cp_wait<0>();
        __syncthreads();
        if (s + 3 < nStages) issueStage((s + 3) << 5, (s + 3) & 3);

        int buf = s & 3;
        unsigned aOff = buf*ABYT, bOff = buf*BBYT;
        #pragma unroll
        for (int kk = 0; kk < 32; kk += 16) {
            unsigned af[4][4];
            #pragma unroll
            for (int mt = 0; mt < 4; mt++)
                ldsm_x4(af[mt], aAddr[mt] + aOff + kk*2);
            #pragma unroll
            for (int ntp = 0; ntp < 4; ntp++) {
                unsigned bfr[4];
                ldsm_x4_t(bfr, bAddr[ntp] + bOff + kk*272);
                #pragma unroll
                for (int mt = 0; mt < 4; mt++) {
                    mma_bf16(acc[mt][ntp*2+0], af[mt], bfr[0], bfr[1]);
                    mma_bf16(acc[mt][ntp*2+1], af[mt], bfr[2], bfr[3]);
                }
            }
        }
    }

    // epilogue
    #pragma unroll
    for (int mt = 0; mt < 4; mt++) {
        int rr0 = warpM*64 + mt*16 + (lane >> 2);
        #pragma unroll
        for (int half = 0; half < 2; half++) {
            int rloc = rr0 + half*8;
            int crow;
            if (GATHER) {
                int pr = rowsS[rloc];
                if (pr < 0) continue;
                crow = pr;
            } else {
                crow = m0 + rloc;
            }
            #pragma unroll
            for (int nt = 0; nt < 8; nt++) {
                int col = n0 + warpN*64 + nt*8 + (lane & 3)*2;
                float v0 = acc[mt][nt][half*2 + 0] + bias[col];
                float v1 = acc[mt][nt][half*2 + 1] + bias[col + 1];
                if (RELU) { v0 = fmaxf(v0, 0.f); v1 = fmaxf(v1, 0.f); }
                if (RESID) {
                    const float* rp = resid + (size_t)crow*ldc + col;
                    v0 += rp[0]; v1 += rp[1];
                }
                if (OUTBF16) {
                    *(bf162*)((bf16*)C + (size_t)crow*ldc + col) =
                        __floats2bfloat162_rn(v0, v1);
                } else {
                    *(float2*)(C + (size_t)crow*ldc + col) = make_float2(v0, v1);
                }
            }
        }
    }
}

// ---------------- tensor-core flash attention (causal, bf16 mma) ----------------
#define ATS 72

__global__ void __launch_bounds__(128) attn_tc_kernel(
    const bf16* __restrict__ q, const bf16* __restrict__ k,
    const bf16* __restrict__ v, bf16* __restrict__ ctx)
{
    __shared__ __align__(16) bf16 Qs[64*ATS];
    __shared__ __align__(16) bf16 Ks[2][64*ATS];
    __shared__ __align__(16) bf16 Vs[2][64*ATS];

    int qt = blockIdx.x, h = blockIdx.y, b = blockIdx.z;
    int q0 = qt * 64;
    int tid = threadIdx.x, lane = tid & 31, w = tid >> 5;

    int srow = tid >> 1;
    int sc0  = (tid & 1) * 4;
    const bf16* qg = q + (size_t)(b*SS + q0 + srow)*DDIM + h*DH + sc0*8;
    unsigned qDst = smem_u32(&Qs[srow*ATS]) + sc0*16;
    unsigned kDst = smem_u32(&Ks[0][srow*ATS]) + sc0*16;
    unsigned vDst = smem_u32(&Vs[0][srow*ATS]) + sc0*16;
    const bf16* kg0 = k + (size_t)(b*SS + srow)*DDIM + h*DH + sc0*8;
    const bf16* vg0 = v + (size_t)(b*SS + srow)*DDIM + h*DH + sc0*8;

    auto issueKV = [&](int kt, int buf) {
        unsigned kd = kDst + buf*(64*ATS*2);
        unsigned vd = vDst + buf*(64*ATS*2);
        const bf16* kgp = kg0 + (size_t)kt*DDIM;
        const bf16* vgp = vg0 + (size_t)kt*DDIM;
        #pragma unroll
        for (int j = 0; j < 4; j++) {
            cp_async16(kd + j*16, kgp + j*8, 16);
            cp_async16(vd + j*16, vgp + j*8, 16);
        }
        cp_commit();
    };

    #pragma unroll
    for (int j = 0; j < 4; j++) cp_async16(qDst + j*16, qg + j*8, 16);
    issueKV(0, 0);

    int l15 = lane & 15;
    int lH8 = (lane >> 4) << 3;
    int lB8 = ((lane >> 3) & 1) << 3;
    int bRowP = lH8 + (lane & 7);

    unsigned qf[4][4];
    float m0 = -1e30f, m1 = -1e30f, l0 = 0.f, l1 = 0.f;
    float oa[8][4];
    #pragma unroll
    for (int j = 0; j < 8; j++)
        #pragma unroll
        for (int e = 0; e < 4; e++) oa[j][e] = 0.f;

    int r0loc = lane >> 2;
    int rowg0 = q0 + 16*w + r0loc;
    int rowg1 = rowg0 + 8;
    int c2 = (lane & 3) * 2;

    int nt = q0/64 + 1;
    for (int t = 0; t < nt; t++) {
        cp_wait<0>();
        __syncthreads();
        if (t == 0) {
            #pragma unroll
            for (int kk = 0; kk < 4; kk++)
                ldsm_x4(qf[kk], smem_u32(&Qs[(16*w + l15)*ATS + kk*16 + lH8]));
        }
        if (t + 1 < nt) issueKV((t+1)*64, (t+1) & 1);

        int buf = t & 1;
        int kt = t * 64;
        const bf16* KsB = Ks[buf];
        const bf16* VsB = Vs[buf];

        float sf[8][4];
        #pragma unroll
        for (int j = 0; j < 8; j++)
            #pragma unroll
            for (int e = 0; e < 4; e++) sf[j][e] = 0.f;
        #pragma unroll
        for (int kk = 0; kk < 4; kk++) {
            #pragma unroll
            for (int j2 = 0; j2 < 4; j2++) {
                unsigned bk[4];
                ldsm_x4(bk, smem_u32(&KsB[(16*j2 + bRowP)*ATS + kk*16 + lB8]));
                mma_bf16(sf[2*j2+0], qf[kk], bk[0], bk[1]);
                mma_bf16(sf[2*j2+1], qf[kk], bk[2], bk[3]);
            }
        }
        #pragma unroll
        for (int j = 0; j < 8; j++)
            #pragma unroll
            for (int e = 0; e < 4; e++) sf[j][e] *= 0.125f;
        if (kt == q0) {
            #pragma unroll
            for (int j = 0; j < 8; j++) {
                int col = kt + 8*j + c2;
                if (col     > rowg0) sf[j][0] = -1e30f;
                if (col + 1 > rowg0) sf[j][1] = -1e30f;
                if (col     > rowg1) sf[j][2] = -1e30f;
                if (col + 1 > rowg1) sf[j][3] = -1e30f;
            }
        }
        float tm0 = -1e30f, tm1 = -1e30f;
        #pragma unroll
        for (int j = 0; j < 8; j++) {
            tm0 = fmaxf(tm0, fmaxf(sf[j][0], sf[j][1]));
            tm1 = fmaxf(tm1, fmaxf(sf[j][2], sf[j][3]));
        }
        tm0 = fmaxf(tm0, __shfl_xor_sync(0xffffffffu, tm0, 1));
        tm0 = fmaxf(tm0, __shfl_xor_sync(0xffffffffu, tm0, 2));
        tm1 = fmaxf(tm1, __shfl_xor_sync(0xffffffffu, tm1, 1));
        tm1 = fmaxf(tm1, __shfl_xor_sync(0xffffffffu, tm1, 2));
        float nm0 = fmaxf(m0, tm0), nm1 = fmaxf(m1, tm1);
        float cc0 = __expf(m0 - nm0), cc1 = __expf(m1 - nm1);
        l0 *= cc0; l1 *= cc1;
        #pragma unroll
        for (int j = 0; j < 8; j++) {
            oa[j][0] *= cc0; oa[j][1] *= cc0;
            oa[j][2] *= cc1; oa[j][3] *= cc1;
        }
        float ps0 = 0.f, ps1 = 0.f;
        #pragma unroll
        for (int j = 0; j < 8; j++) {
            sf[j][0] = __expf(sf[j][0] - nm0);
            sf[j][1] = __expf(sf[j][1] - nm0);
            sf[j][2] = __expf(sf[j][2] - nm1);
            sf[j][3] = __expf(sf[j][3] - nm1);
            ps0 += sf[j][0] + sf[j][1];
            ps1 += sf[j][2] + sf[j][3];
        }
        l0 += ps0; l1 += ps1; m0 = nm0; m1 = nm1;

        unsigned pf[4][4];
        #pragma unroll
        for (int t2 = 0; t2 < 4; t2++) {
            pf[t2][0] = pack_bf16(sf[2*t2][0],   sf[2*t2][1]);
            pf[t2][1] = pack_bf16(sf[2*t2][2],   sf[2*t2][3]);
            pf[t2][2] = pack_bf16(sf[2*t2+1][0], sf[2*t2+1][1]);
            pf[t2][3] = pack_bf16(sf[2*t2+1][2], sf[2*t2+1][3]);
        }
        #pragma unroll
        for (int t2 = 0; t2 < 4; t2++) {
            #pragma unroll
            for (int g = 0; g < 4; g++) {
                unsigned bv[4];
                ldsm_x4_t(bv, smem_u32(&VsB[(16*t2 + l15)*ATS + 16*g + lH8]));
                mma_bf16(oa[2*g+0], pf[t2], bv[0], bv[1]);
                mma_bf16(oa[2*g+1], pf[t2], bv[2], bv[3]);
            }
        }
        __syncthreads();
    }

    l0 += __shfl_xor_sync(0xffffffffu, l0, 1);
    l0 += __shfl_xor_sync(0xffffffffu, l0, 2);
    l1 += __shfl_xor_sync(0xffffffffu, l1, 1);
    l1 += __shfl_xor_sync(0xffffffffu, l1, 2);
    float inv0 = 1.f / l0, inv1 = 1.f / l1;

    bf16* c0p = ctx + (size_t)(b*SS + rowg0)*DDIM + h*DH + c2;
    bf16* c1p = ctx + (size_t)(b*SS + rowg1)*DDIM + h*DH + c2;
    #pragma unroll
    for (int j = 0; j < 8; j++) {
        *(bf162*)(c0p + 8*j) = __floats2bfloat162_rn(oa[j][0]*inv0, oa[j][1]*inv0);
        *(bf162*)(c1p + 8*j) = __floats2bfloat162_rn(oa[j][2]*inv1, oa[j][3]*inv1);
    }
}

// ---------------- gate ----------------
__global__ void zero_cnt_kernel(int* cnt) {
    if (threadIdx.x < EE) cnt[threadIdx.x] = 0;
}

__global__ void gate_kernel(const float* __restrict__ h, const float* __restrict__ gw,
                            const float* __restrict__ gb, float* __restrict__ sc,
                            int* __restrict__ cnt, int* __restrict__ list)
{
    int warp = (blockIdx.x * blockDim.x + threadIdx.x) >> 5;
    if (warp >= NTOK) return;
    int lane = threadIdx.x & 31;
    float a[8] = {0,0,0,0,0,0,0,0};
    const float* hr = h + (size_t)warp * DDIM;
    for (int d = lane; d < DDIM; d += 32) {
        float hv = hr[d];
        float4 w0 = *(const float4*)(gw + (size_t)d*EE);
        float4 w1 = *(const float4*)(gw + (size_t)d*EE + 4);
        a[0]+=hv*w0.x; a[1]+=hv*w0.y; a[2]+=hv*w0.z; a[3]+=hv*w0.w;
        a[4]+=hv*w1.x; a[5]+=hv*w1.y; a[6]+=hv*w1.z; a[7]+=hv*w1.w;
    }
    #pragma unroll
    for (int e = 0; e < 8; e++)
        #pragma unroll
        for (int o = 16; o > 0; o >>= 1)
            a[e] += __shfl_down_sync(0xffffffffu, a[e], o);
    if (lane == 0) {
        float lg[8];
        #pragma unroll
        for (int e = 0; e < 8; e++) lg[e] = a[e] + gb[e];
        int i0 = 0; float v0 = lg[0];
        #pragma unroll
        for (int e = 1; e < 8; e++) if (lg[e] > v0) { v0 = lg[e]; i0 = e; }
        int i1 = -1; float v1 = -3.0e38f;
        #pragma unroll
        for (int e = 0; e < 8; e++) if (e != i0 && lg[e] > v1) { v1 = lg[e]; i1 = e; }
        float e1 = __expf(v1 - v0);
        float s0 = 1.f / (1.f + e1);
        float s1 = e1 * s0;
        sc[2*warp]   = s0;
        sc[2*warp+1] = s1;
        int p0 = atomicAdd(&cnt[i0], 1);
        list[(size_t)i0*CAP + p0] = 2*warp;
        int p1 = atomicAdd(&cnt[i1], 1);
        list[(size_t)i1*CAP + p1] = 2*warp + 1;
    }
}

// ---------------- combine ----------------
__global__ void combine_kernel(const float* __restrict__ h, const float* __restrict__ o2,
                               const float* __restrict__ sc, const float* __restrict__ xa,
                               const float* __restrict__ g, const float* __restrict__ b,
                               float* __restrict__ out)
{
    int t = blockIdx.x;
    const float* hr = h + (size_t)t*DDIM;
    const float* r0 = o2 + (size_t)(2*t)*DDIM;
    const float* r1 = o2 + (size_t)(2*t+1)*DDIM;
    float s0 = sc[2*t], s1 = sc[2*t+1];
    float tv[3];
    float s = 0.f;
    #pragma unroll
    for (int i = 0; i < 3; i++) {
        int d = threadIdx.x + i*256;
        tv[i] = hr[d] + s0*r0[d] + s1*r1[d];
        s += tv[i];
    }
    s = blockReduceSum(s);
    float mean = s * (1.f / DDIM);
    float vs = 0.f;
    #pragma unroll
    for (int i = 0; i < 3; i++) { float d = tv[i] - mean; vs += d*d; }
    vs = blockReduceSum(vs);
    float rstd = rsqrtf(vs * (1.f / DDIM) + 1e-5f);
    #pragma unroll
    for (int i = 0; i < 3; i++) {
        int d = threadIdx.x + i*256;
        out[(size_t)t*DDIM + d] = xa[(size_t)t*DDIM + d] + (tv[i] - mean)*rstd*g[d] + b[d];
    }
}

// ---------------- launch ----------------
extern "C" void kernel_launch(void* const* d_in, const int* in_sizes, int n_in,
                              void* d_out, int out_size)
{
    const float* x        = (const float*)d_in[0];
    const float* ln_a_g   = (const float*)d_in[2];
    const float* ln_a_b   = (const float*)d_in[3];
    const float* wq       = (const float*)d_in[4];
    const float* bq       = (const float*)d_in[5];
    const float* wk       = (const float*)d_in[6];
    const float* bk       = (const float*)d_in[7];
    const float* wv       = (const float*)d_in[8];
    const float* bv       = (const float*)d_in[9];
    const float* wo       = (const float*)d_in[10];
    const float* bo       = (const float*)d_in[11];
    const float* ln_f_g   = (const float*)d_in[12];
    const float* ln_f_b   = (const float*)d_in[13];
    const float* gate_w   = (const float*)d_in[14];
    const float* gate_b   = (const float*)d_in[15];
    const float* w1       = (const float*)d_in[16];
    const float* b1       = (const float*)d_in[17];
    const float* w2       = (const float*)d_in[18];
    const float* b2       = (const float*)d_in[19];
    const float* moe_g    = (const float*)d_in[20];
    const float* moe_b    = (const float*)d_in[21];
    float* out = (float*)d_out;

    bf16 *a, *qb, *kb, *vb, *ctx, *hrb, *y1, *bwq, *bwk, *bwv, *bwo, *bw1, *bw2;
    float *xa, *h, *o2, *sc;
    int *cnt, *list;
    cudaGetSymbolAddress((void**)&a,   g_a);
    cudaGetSymbolAddress((void**)&qb,  g_q);
    cudaGetSymbolAddress((void**)&kb,  g_k);
    cudaGetSymbolAddress((void**)&vb,  g_v);
    cudaGetSymbolAddress((void**)&ctx, g_ctx);
    cudaGetSymbolAddress((void**)&xa,  g_xa);
    cudaGetSymbolAddress((void**)&h,   g_h);
    cudaGetSymbolAddress((void**)&hrb, g_hr);
    cudaGetSymbolAddress((void**)&y1,  g_y1);
    cudaGetSymbolAddress((void**)&o2,  g_o2);
    cudaGetSymbolAddress((void**)&sc,  g_sc);
    cudaGetSymbolAddress((void**)&cnt, g_cnt);
    cudaGetSymbolAddress((void**)&list,g_list);
    cudaGetSymbolAddress((void**)&bwq, g_bwq);
    cudaGetSymbolAddress((void**)&bwk, g_bwk);
    cudaGetSymbolAddress((void**)&bwv, g_bwv);
    cudaGetSymbolAddress((void**)&bwo, g_bwo);
    cudaGetSymbolAddress((void**)&bw1, g_bw1);
    cudaGetSymbolAddress((void**)&bw2, g_bw2);

    cudaFuncSetAttribute(bgemm_k<false,false,false,false,true,true>,
                         cudaFuncAttributeMaxDynamicSharedMemorySize, GSMEM);
    cudaFuncSetAttribute(bgemm_k<false,false,false,true,false,false>,
                         cudaFuncAttributeMaxDynamicSharedMemorySize, GSMEM);
    cudaFuncSetAttribute(bgemm_k<true,false,true,false,true,false>,
                         cudaFuncAttributeMaxDynamicSharedMemorySize, GSMEM);
    cudaFuncSetAttribute(bgemm_k<true,true,false,false,false,false>,
                         cudaFuncAttributeMaxDynamicSharedMemorySize, GSMEM);

    // 0) weight conversions f32 -> bf16
    {
        int nqkv4 = DDIM*DDIM/4;
        int gq = (nqkv4 + 255)/256;
        conv_bf16_kernel<<<gq, 256>>>(wq, bwq, nqkv4);
        conv_bf16_kernel<<<gq, 256>>>(wk, bwk, nqkv4);
        conv_bf16_kernel<<<gq, 256>>>(wv, bwv, nqkv4);
        conv_bf16_kernel<<<gq, 256>>>(wo, bwo, nqkv4);
        int nff4 = EE*DDIM*HID/4;
        int gf = (nff4 + 255)/256;
        conv_bf16_kernel<<<gf, 256>>>(w1, bw1, nff4);
        conv_bf16_kernel<<<gf, 256>>>(w2, bw2, nff4);
    }

    // 1) a = bf16(ln_attn(x))
    ln_kernel<1><<<NTOK, 256>>>(x, ln_a_g, ln_a_b, nullptr, a);

    // 2) fused q,k,v projections -> bf16 outputs
    dim3 gQKV(DDIM/128, NTOK/256, 3);
    bgemm_k<false,false,false,false,true,true><<<gQKV, 256, GSMEM>>>(
        NTOK, DDIM, DDIM, a, DDIM, bwq, bq, nullptr, (float*)qb, DDIM, nullptr, nullptr,
        bwk, bk, (float*)kb, bwv, bv, (float*)vb);

    // 3) tensor-core flash attention (causal), ctx bf16
    attn_tc_kernel<<<dim3(SS/64, HH, BB), 128>>>(qb, kb, vb, ctx);

    // 4) xa = x + ctx @ wo + bo
    dim3 gO(DDIM/128, NTOK/256, 1);
    bgemm_k<false,false,false,true,false,false><<<gO, 256, GSMEM>>>(
        NTOK, DDIM, DDIM, ctx, DDIM, bwo, bo, x, xa, DDIM, nullptr, nullptr,
        nullptr, nullptr, nullptr, nullptr, nullptr, nullptr);

    // 5) h = ln_ff(xa) (f32) + hr (bf16)
    ln_kernel<2><<<NTOK, 256>>>(xa, ln_f_g, ln_f_b, h, hrb);

    // 6) gate: top-2 per token + per-expert pair lists
    zero_cnt_kernel<<<1, 32>>>(cnt);
    gate_kernel<<<NTOK/8, 256>>>(h, gate_w, gate_b, sc, cnt, list);

    // 7) expert GEMM1: y1[pair] = bf16(relu(hr[token] @ w1[e] + b1[e]))
    bgemm_k<true,false,true,false,true,false><<<dim3(HID/128, CAP/256, EE), 256, GSMEM>>>(
        CAP, HID, DDIM, hrb, DDIM, bw1, b1, nullptr, (float*)y1, HID, list, cnt,
        nullptr, nullptr, nullptr, nullptr, nullptr, nullptr);

    // 8) expert GEMM2: o2[pair] = y1[pair] @ w2[e] + b2[e]
    bgemm_k<true,true,false,false,false,false><<<dim3(DDIM/128, CAP/256, EE), 256, GSMEM>>>(
        CAP, DDIM, HID, y1, HID, bw2, b2, nullptr, o2, DDIM, list, cnt,
        nullptr, nullptr, nullptr, nullptr, nullptr, nullptr);

    // 9) combine + post-LN + final residual
    combine_kernel<<<NTOK, 256>>>(h, o2, sc, xa, moe_g, moe_b, out);
}

// round 13
// speedup vs baseline: 1.0288x; 1.0288x over previous
#include <cuda_runtime.h>
#include <cuda_bf16.h>

#define BB 4
#define SS 1024
#define DDIM 768
#define HH 12
#define EE 8
#define HID 3072
#define DH 64
#define NTOK (BB*SS)
#define CAP (NTOK*2)

typedef __nv_bfloat16 bf16;
typedef __nv_bfloat162 bf162;

// ---------------- scratch ----------------
__device__ bf16  g_a[NTOK*DDIM];
__device__ bf16  g_q[NTOK*DDIM];
__device__ bf16  g_k[NTOK*DDIM];
__device__ bf16  g_v[NTOK*DDIM];
__device__ bf16  g_ctx[NTOK*DDIM];
__device__ float g_xa[NTOK*DDIM];
__device__ float g_h[NTOK*DDIM];
__device__ bf16  g_hr[NTOK*DDIM];
__device__ bf16  g_y1[CAP*HID];
__device__ float g_o2[CAP*DDIM];
__device__ float g_sc[CAP];
__device__ int   g_cnt[EE];
__device__ int   g_list[EE*CAP];
__device__ bf16  g_bwq[DDIM*DDIM];
__device__ bf16  g_bwk[DDIM*DDIM];
__device__ bf16  g_bwv[DDIM*DDIM];
__device__ bf16  g_bwo[DDIM*DDIM];
__device__ bf16  g_bw1[EE*DDIM*HID];
__device__ bf16  g_bw2[EE*HID*DDIM];

// ---------------- helpers ----------------
__device__ __forceinline__ unsigned smem_u32(const void* p) {
    return (unsigned)__cvta_generic_to_shared(p);
}
__device__ __forceinline__ void cp_async16(unsigned dst, const void* src, int srcsize) {
    asm volatile("cp.async.cg.shared.global [%0], [%1], 16, %2;"
                 :: "r"(dst), "l"(src), "r"(srcsize));
}
__device__ __forceinline__ void cp_commit() { asm volatile("cp.async.commit_group;"); }
template<int N>
__device__ __forceinline__ void cp_wait() { asm volatile("cp.async.wait_group %0;" :: "n"(N)); }

__device__ __forceinline__ void ldsm_x4(unsigned* r, unsigned addr) {
    asm volatile("ldmatrix.sync.aligned.m8n8.x4.shared.b16 {%0,%1,%2,%3}, [%4];"
        : "=r"(r[0]), "=r"(r[1]), "=r"(r[2]), "=r"(r[3]) : "r"(addr));
}
__device__ __forceinline__ void ldsm_x4_t(unsigned* r, unsigned addr) {
    asm volatile("ldmatrix.sync.aligned.m8n8.x4.trans.shared.b16 {%0,%1,%2,%3}, [%4];"
        : "=r"(r[0]), "=r"(r[1]), "=r"(r[2]), "=r"(r[3]) : "r"(addr));
}
__device__ __forceinline__ void mma_bf16(float c[4], const unsigned a[4],
                                         unsigned b0, unsigned b1) {
    asm volatile("mma.sync.aligned.m16n8k16.row.col.f32.bf16.bf16.f32 "
        "{%0,%1,%2,%3}, {%4,%5,%6,%7}, {%8,%9}, {%0,%1,%2,%3};"
        : "+f"(c[0]), "+f"(c[1]), "+f"(c[2]), "+f"(c[3])
        : "r"(a[0]), "r"(a[1]), "r"(a[2]), "r"(a[3]), "r"(b0), "r"(b1));
}
__device__ __forceinline__ unsigned pack_bf16(float a, float b) {
    bf162 t = __floats2bfloat162_rn(a, b);
    return *(unsigned*)&t;
}

__device__ __forceinline__ float blockReduceSum(float v) {
    __shared__ float sh[33];
    __syncthreads();
    int lane = threadIdx.x & 31, wid = threadIdx.x >> 5;
    #pragma unroll
    for (int o = 16; o > 0; o >>= 1) v += __shfl_down_sync(0xffffffffu, v, o);
    if (lane == 0) sh[wid] = v;
    __syncthreads();
    float r = (threadIdx.x < (blockDim.x >> 5)) ? sh[threadIdx.x] : 0.f;
    if (wid == 0) {
        #pragma unroll
        for (int o = 16; o > 0; o >>= 1) r += __shfl_down_sync(0xffffffffu, r, o);
        if (lane == 0) sh[32] = r;
    }
    __syncthreads();
    return sh[32];
}

// ---------------- weight conversion f32 -> bf16 ----------------
__global__ void conv_bf16_kernel(const float* __restrict__ src, bf16* __restrict__ dst, int n4) {
    int i = blockIdx.x * blockDim.x + threadIdx.x;
    if (i < n4) {
        float4 v = *(const float4*)(src + (size_t)i*4);
        bf162* d = (bf162*)(dst + (size_t)i*4);
        d[0] = __floats2bfloat162_rn(v.x, v.y);
        d[1] = __floats2bfloat162_rn(v.z, v.w);
    }
}

// ---------------- layernorm ----------------
template<int MODE>
__global__ void ln_kernel(const float* __restrict__ x, const float* __restrict__ g,
                          const float* __restrict__ b, float* __restrict__ out,
                          bf16* __restrict__ out_b) {
    int row = blockIdx.x;
    const float* xr = x + (size_t)row * DDIM;
    float v[3];
    float s = 0.f;
    #pragma unroll
    for (int i = 0; i < 3; i++) { v[i] = xr[threadIdx.x + i*256]; s += v[i]; }
    s = blockReduceSum(s);
    float mean = s * (1.f / DDIM);
    float vs = 0.f;
    #pragma unroll
    for (int i = 0; i < 3; i++) { float d = v[i] - mean; vs += d*d; }
    vs = blockReduceSum(vs);
    float rstd = rsqrtf(vs * (1.f / DDIM) + 1e-5f);
    #pragma unroll
    for (int i = 0; i < 3; i++) {
        int d = threadIdx.x + i*256;
        float y = (v[i] - mean) * rstd * g[d] + b[d];
        if (MODE == 1) out_b[(size_t)row*DDIM + d] = __float2bfloat16_rn(y);
        if (MODE == 2) {
            out  [(size_t)row*DDIM + d] = y;
            out_b[(size_t)row*DDIM + d] = __float2bfloat16_rn(y);
        }
    }
}

// ---------------- bf16 tensor-core GEMM: 128x128 CTA, 4 warps, 64x64 warp tile ----------------
// BK=32, 4-stage cp.async pipeline, 128 threads, 2 CTAs/SM.
// A smem: [128 rows][32 bf16] stride 40; B smem: [32 k][128 n] stride 136.
#define ABYT 10240   /* 128*40*2 */
#define BBYT 8704    /* 32*136*2 */
#define GSMEM (4*(ABYT + BBYT) + 512)

template<bool GATHER, bool AROW_PAIR, bool RELU, bool RESID, bool OUTBF16, bool QKV3>
__global__ __launch_bounds__(128, 2) void bgemm_k(
    int M, int N, int K,
    const bf16* __restrict__ A, int lda,
    const bf16* __restrict__ Bm,
    const float* __restrict__ bias,
    const float* __restrict__ resid,
    float* __restrict__ C, int ldc,
    const int* __restrict__ rowlist,
    const int* __restrict__ cnt,
    const bf16* Bm2, const float* bias2, float* C2,
    const bf16* Bm3, const float* bias3, float* C3)
{
    extern __shared__ __align__(16) char smem_raw[];
    bf16* AsBase = (bf16*)smem_raw;                    // 4 * ABYT
    bf16* BsBase = (bf16*)(smem_raw + 4*ABYT);         // 4 * BBYT
    int*  rowsS  = (int*)(smem_raw + 4*(ABYT + BBYT)); // 128 ints

    if (QKV3) {
        int z = blockIdx.z;
        if (z == 1) { Bm = Bm2; bias = bias2; C = C2; }
        else if (z == 2) { Bm = Bm3; bias = bias3; C = C3; }
    }
    if (GATHER) {
        int e = blockIdx.z;
        Bm      += (size_t)e * K * N;
        bias    += (size_t)e * N;
        rowlist += (size_t)e * CAP;
        cnt     += e;
    }
    int m0 = blockIdx.y * 128, n0 = blockIdx.x * 128;
    int tid = threadIdx.x, lane = tid & 31, wid = tid >> 5;
    int warpM = wid & 1, warpN = wid >> 1;

    if (GATHER) {
        int Meff = *cnt;
        if (m0 >= Meff) return;
        int gidx = m0 + tid;
        rowsS[tid] = (gidx < Meff) ? rowlist[gidx] : -1;
        __syncthreads();
    }

    // ---- A staging: thread -> row tid, 4 chunks of 16B (32 bf16/row/stage) ----
    const bf16* Aptr;
    int asz = 16;
    if (GATHER) {
        int pr = rowsS[tid];
        if (pr < 0) { Aptr = A; asz = 0; }
        else Aptr = A + (size_t)(AROW_PAIR ? pr : (pr >> 1)) * lda;
    } else {
        Aptr = A + (size_t)(m0 + tid) * lda;
    }
    unsigned aD0 = smem_u32(&AsBase[tid*40]);

    // ---- B staging: thread -> k-row tid>>2, 32 elems at (tid&3)*32 ----
    int lbr = tid >> 2;
    int bce = (tid & 3) << 5;
    const bf16* Bptr = Bm + (size_t)lbr * N + n0 + bce;
    unsigned bD0 = smem_u32(&BsBase[lbr*136 + bce]);

    // ---- ldmatrix addresses ----
    int lane8 = lane & 7, laneH = lane & 8, laneK = (lane & 16) >> 1;
    unsigned aAddr[4], bAddr[4];
    #pragma unroll
    for (int mt = 0; mt < 4; mt++) {
        int r = warpM*64 + mt*16 + lane8 + laneH;
        aAddr[mt] = smem_u32(&AsBase[r*40 + laneK]);
    }
    #pragma unroll
    for (int ntp = 0; ntp < 4; ntp++) {
        int kr = lane8 + laneH;
        int nc = warpN*64 + ntp*16 + laneK;
        bAddr[ntp] = smem_u32(&BsBase[kr*136 + nc]);
    }

    float acc[4][8][4];
    #pragma unroll
    for (int i = 0; i < 4; i++)
        #pragma unroll
        for (int j = 0; j < 8; j++)
            #pragma unroll
            for (int q = 0; q < 4; q++) acc[i][j][q] = 0.f;

    auto issueStage = [&](int k0, int buf) {
        unsigned ad = aD0 + buf*ABYT;
        const bf16* ap = Aptr + k0;
        #pragma unroll
        for (int j = 0; j < 4; j++) cp_async16(ad + j*16, ap + j*8, asz);
        unsigned bd = bD0 + buf*BBYT;
        const bf16* bp = Bptr + (size_t)k0 * N;
        #pragma unroll
        for (int j = 0; j < 4; j++) cp_async16(bd + j*16, bp + j*8, 16);
        cp_commit();
    };

    int nStages = K >> 5;
    issueStage(0, 0);
    issueStage(32, 1);
    issueStage(64, 2);

    for (int s = 0; s < nStages; s++) {
        int rem = nStages - 1 - s;
        if (rem >= 2) cp_wait<2>();
        else if (rem == 1) cp_wait<1>();
        else cp_wait<0>();
        __syncthreads();
        if (s + 3 < nStages) issueStage((s + 3) << 5, (s + 3) & 3);

        int buf = s & 3;
        unsigned aOff = buf*ABYT, bOff = buf*BBYT;
        #pragma unroll
        for (int kk = 0; kk < 32; kk += 16) {
            unsigned af[4][4];
            #pragma unroll
            for (int mt = 0; mt < 4; mt++)
                ldsm_x4(af[mt], aAddr[mt] + aOff + kk*2);
            #pragma unroll
            for (int ntp = 0; ntp < 4; ntp++) {
                unsigned bfr[4];
                ldsm_x4_t(bfr, bAddr[ntp] + bOff + kk*272);
                #pragma unroll
                for (int mt = 0; mt < 4; mt++) {
                    mma_bf16(acc[mt][ntp*2+0], af[mt], bfr[0], bfr[1]);
                    mma_bf16(acc[mt][ntp*2+1], af[mt], bfr[2], bfr[3]);
                }
            }
        }
    }

    // epilogue
    #pragma unroll
    for (int mt = 0; mt < 4; mt++) {
        int rr0 = warpM*64 + mt*16 + (lane >> 2);
        #pragma unroll
        for (int half = 0; half < 2; half++) {
            int rloc = rr0 + half*8;
            int crow;
            if (GATHER) {
                int pr = rowsS[rloc];
                if (pr < 0) continue;
                crow = pr;
            } else {
                crow = m0 + rloc;
            }
            #pragma unroll
            for (int nt = 0; nt < 8; nt++) {
                int col = n0 + warpN*64 + nt*8 + (lane & 3)*2;
                float v0 = acc[mt][nt][half*2 + 0] + bias[col];
                float v1 = acc[mt][nt][half*2 + 1] + bias[col + 1];
                if (RELU) { v0 = fmaxf(v0, 0.f); v1 = fmaxf(v1, 0.f); }
                if (RESID) {
                    const float* rp = resid + (size_t)crow*ldc + col;
                    v0 += rp[0]; v1 += rp[1];
                }
                if (OUTBF16) {
                    *(bf162*)((bf16*)C + (size_t)crow*ldc + col) =
                        __floats2bfloat162_rn(v0, v1);
                } else {
                    *(float2*)(C + (size_t)crow*ldc + col) = make_float2(v0, v1);
                }
            }
        }
    }
}

// ---------------- tensor-core flash attention (causal, bf16 mma) ----------------
#define ATS 72

__global__ void __launch_bounds__(128) attn_tc_kernel(
    const bf16* __restrict__ q, const bf16* __restrict__ k,
    const bf16* __restrict__ v, bf16* __restrict__ ctx)
{
    __shared__ __align__(16) bf16 Qs[64*ATS];
    __shared__ __align__(16) bf16 Ks[2][64*ATS];
    __shared__ __align__(16) bf16 Vs[2][64*ATS];

    int qt = blockIdx.x, h = blockIdx.y, b = blockIdx.z;
    int q0 = qt * 64;
    int tid = threadIdx.x, lane = tid & 31, w = tid >> 5;

    int srow = tid >> 1;
    int sc0  = (tid & 1) * 4;
    const bf16* qg = q + (size_t)(b*SS + q0 + srow)*DDIM + h*DH + sc0*8;
    unsigned qDst = smem_u32(&Qs[srow*ATS]) + sc0*16;
    unsigned kDst = smem_u32(&Ks[0][srow*ATS]) + sc0*16;
    unsigned vDst = smem_u32(&Vs[0][srow*ATS]) + sc0*16;
    const bf16* kg0 = k + (size_t)(b*SS + srow)*DDIM + h*DH + sc0*8;
    const bf16* vg0 = v + (size_t)(b*SS + srow)*DDIM + h*DH + sc0*8;

    auto issueKV = [&](int kt, int buf) {
        unsigned kd = kDst + buf*(64*ATS*2);
        unsigned vd = vDst + buf*(64*ATS*2);
        const bf16* kgp = kg0 + (size_t)kt*DDIM;
        const bf16* vgp = vg0 + (size_t)kt*DDIM;
        #pragma unroll
        for (int j = 0; j < 4; j++) {
            cp_async16(kd + j*16, kgp + j*8, 16);
            cp_async16(vd + j*16, vgp + j*8, 16);
        }
        cp_commit();
    };

    #pragma unroll
    for (int j = 0; j < 4; j++) cp_async16(qDst + j*16, qg + j*8, 16);
    issueKV(0, 0);

    int l15 = lane & 15;
    int lH8 = (lane >> 4) << 3;
    int lB8 = ((lane >> 3) & 1) << 3;
    int bRowP = lH8 + (lane & 7);

    unsigned qf[4][4];
    float m0 = -1e30f, m1 = -1e30f, l0 = 0.f, l1 = 0.f;
    float oa[8][4];
    #pragma unroll
    for (int j = 0; j < 8; j++)
        #pragma unroll
        for (int e = 0; e < 4; e++) oa[j][e] = 0.f;

    int r0loc = lane >> 2;
    int rowg0 = q0 + 16*w + r0loc;
    int rowg1 = rowg0 + 8;
    int c2 = (lane & 3) * 2;

    int nt = q0/64 + 1;
    for (int t = 0; t < nt; t++) {
        cp_wait<0>();
        __syncthreads();
        if (t == 0) {
            #pragma unroll
            for (int kk = 0; kk < 4; kk++)
                ldsm_x4(qf[kk], smem_u32(&Qs[(16*w + l15)*ATS + kk*16 + lH8]));
        }
        if (t + 1 < nt) issueKV((t+1)*64, (t+1) & 1);

        int buf = t & 1;
        int kt = t * 64;
        const bf16* KsB = Ks[buf];
        const bf16* VsB = Vs[buf];

        float sf[8][4];
        #pragma unroll
        for (int j = 0; j < 8; j++)
            #pragma unroll
            for (int e = 0; e < 4; e++) sf[j][e] = 0.f;
        #pragma unroll
        for (int kk = 0; kk < 4; kk++) {
            #pragma unroll
            for (int j2 = 0; j2 < 4; j2++) {
                unsigned bk[4];
                ldsm_x4(bk, smem_u32(&KsB[(16*j2 + bRowP)*ATS + kk*16 + lB8]));
                mma_bf16(sf[2*j2+0], qf[kk], bk[0], bk[1]);
                mma_bf16(sf[2*j2+1], qf[kk], bk[2], bk[3]);
            }
        }
        #pragma unroll
        for (int j = 0; j < 8; j++)
            #pragma unroll
            for (int e = 0; e < 4; e++) sf[j][e] *= 0.125f;
        if (kt == q0) {
            #pragma unroll
            for (int j = 0; j < 8; j++) {
                int col = kt + 8*j + c2;
                if (col     > rowg0) sf[j][0] = -1e30f;
                if (col + 1 > rowg0) sf[j][1] = -1e30f;
                if (col     > rowg1) sf[j][2] = -1e30f;
                if (col + 1 > rowg1) sf[j][3] = -1e30f;
            }
        }
        float tm0 = -1e30f, tm1 = -1e30f;
        #pragma unroll
        for (int j = 0; j < 8; j++) {
            tm0 = fmaxf(tm0, fmaxf(sf[j][0], sf[j][1]));
            tm1 = fmaxf(tm1, fmaxf(sf[j][2], sf[j][3]));
        }
        tm0 = fmaxf(tm0, __shfl_xor_sync(0xffffffffu, tm0, 1));
        tm0 = fmaxf(tm0, __shfl_xor_sync(0xffffffffu, tm0, 2));
        tm1 = fmaxf(tm1, __shfl_xor_sync(0xffffffffu, tm1, 1));
        tm1 = fmaxf(tm1, __shfl_xor_sync(0xffffffffu, tm1, 2));
        float nm0 = fmaxf(m0, tm0), nm1 = fmaxf(m1, tm1);
        float cc0 = __expf(m0 - nm0), cc1 = __expf(m1 - nm1);
        l0 *= cc0; l1 *= cc1;
        #pragma unroll
        for (int j = 0; j < 8; j++) {
            oa[j][0] *= cc0; oa[j][1] *= cc0;
            oa[j][2] *= cc1; oa[j][3] *= cc1;
        }
        float ps0 = 0.f, ps1 = 0.f;
        #pragma unroll
        for (int j = 0; j < 8; j++) {
            sf[j][0] = __expf(sf[j][0] - nm0);
            sf[j][1] = __expf(sf[j][1] - nm0);
            sf[j][2] = __expf(sf[j][2] - nm1);
            sf[j][3] = __expf(sf[j][3] - nm1);
            ps0 += sf[j][0] + sf[j][1];
            ps1 += sf[j][2] + sf[j][3];
        }
        l0 += ps0; l1 += ps1; m0 = nm0; m1 = nm1;

        unsigned pf[4][4];
        #pragma unroll
        for (int t2 = 0; t2 < 4; t2++) {
            pf[t2][0] = pack_bf16(sf[2*t2][0],   sf[2*t2][1]);
            pf[t2][1] = pack_bf16(sf[2*t2][2],   sf[2*t2][3]);
            pf[t2][2] = pack_bf16(sf[2*t2+1][0], sf[2*t2+1][1]);
            pf[t2][3] = pack_bf16(sf[2*t2+1][2], sf[2*t2+1][3]);
        }
        #pragma unroll
        for (int t2 = 0; t2 < 4; t2++) {
            #pragma unroll
            for (int g = 0; g < 4; g++) {
                unsigned bv[4];
                ldsm_x4_t(bv, smem_u32(&VsB[(16*t2 + l15)*ATS + 16*g + lH8]));
                mma_bf16(oa[2*g+0], pf[t2], bv[0], bv[1]);
                mma_bf16(oa[2*g+1], pf[t2], bv[2], bv[3]);
            }
        }
        __syncthreads();
    }

    l0 += __shfl_xor_sync(0xffffffffu, l0, 1);
    l0 += __shfl_xor_sync(0xffffffffu, l0, 2);
    l1 += __shfl_xor_sync(0xffffffffu, l1, 1);
    l1 += __shfl_xor_sync(0xffffffffu, l1, 2);
    float inv0 = 1.f / l0, inv1 = 1.f / l1;

    bf16* c0p = ctx + (size_t)(b*SS + rowg0)*DDIM + h*DH + c2;
    bf16* c1p = ctx + (size_t)(b*SS + rowg1)*DDIM + h*DH + c2;
    #pragma unroll
    for (int j = 0; j < 8; j++) {
        *(bf162*)(c0p + 8*j) = __floats2bfloat162_rn(oa[j][0]*inv0, oa[j][1]*inv0);
        *(bf162*)(c1p + 8*j) = __floats2bfloat162_rn(oa[j][2]*inv1, oa[j][3]*inv1);
    }
}

// ---------------- gate ----------------
__global__ void zero_cnt_kernel(int* cnt) {
    if (threadIdx.x < EE) cnt[threadIdx.x] = 0;
}

__global__ void gate_kernel(const float* __restrict__ h, const float* __restrict__ gw,
                            const float* __restrict__ gb, float* __restrict__ sc,
                            int* __restrict__ cnt, int* __restrict__ list)
{
    int warp = (blockIdx.x * blockDim.x + threadIdx.x) >> 5;
    if (warp >= NTOK) return;
    int lane = threadIdx.x & 31;
    float a[8] = {0,0,0,0,0,0,0,0};
    const float* hr = h + (size_t)warp * DDIM;
    for (int d = lane; d < DDIM; d += 32) {
        float hv = hr[d];
        float4 w0 = *(const float4*)(gw + (size_t)d*EE);
        float4 w1 = *(const float4*)(gw + (size_t)d*EE + 4);
        a[0]+=hv*w0.x; a[1]+=hv*w0.y; a[2]+=hv*w0.z; a[3]+=hv*w0.w;
        a[4]+=hv*w1.x; a[5]+=hv*w1.y; a[6]+=hv*w1.z; a[7]+=hv*w1.w;
    }
    #pragma unroll
    for (int e = 0; e < 8; e++)
        #pragma unroll
        for (int o = 16; o > 0; o >>= 1)
            a[e] += __shfl_down_sync(0xffffffffu, a[e], o);
    if (lane == 0) {
        float lg[8];
        #pragma unroll
        for (int e = 0; e < 8; e++) lg[e] = a[e] + gb[e];
        int i0 = 0; float v0 = lg[0];
        #pragma unroll
        for (int e = 1; e < 8; e++) if (lg[e] > v0) { v0 = lg[e]; i0 = e; }
        int i1 = -1; float v1 = -3.0e38f;
        #pragma unroll
        for (int e = 0; e < 8; e++) if (e != i0 && lg[e] > v1) { v1 = lg[e]; i1 = e; }
        float e1 = __expf(v1 - v0);
        float s0 = 1.f / (1.f + e1);
        float s1 = e1 * s0;
        sc[2*warp]   = s0;
        sc[2*warp+1] = s1;
        int p0 = atomicAdd(&cnt[i0], 1);
        list[(size_t)i0*CAP + p0] = 2*warp;
        int p1 = atomicAdd(&cnt[i1], 1);
        list[(size_t)i1*CAP + p1] = 2*warp + 1;
    }
}

// ---------------- combine ----------------
__global__ void combine_kernel(const float* __restrict__ h, const float* __restrict__ o2,
                               const float* __restrict__ sc, const float* __restrict__ xa,
                               const float* __restrict__ g, const float* __restrict__ b,
                               float* __restrict__ out)
{
    int t = blockIdx.x;
    const float* hr = h + (size_t)t*DDIM;
    const float* r0 = o2 + (size_t)(2*t)*DDIM;
    const float* r1 = o2 + (size_t)(2*t+1)*DDIM;
    float s0 = sc[2*t], s1 = sc[2*t+1];
    float tv[3];
    float s = 0.f;
    #pragma unroll
    for (int i = 0; i < 3; i++) {
        int d = threadIdx.x + i*256;
        tv[i] = hr[d] + s0*r0[d] + s1*r1[d];
        s += tv[i];
    }
    s = blockReduceSum(s);
    float mean = s * (1.f / DDIM);
    float vs = 0.f;
    #pragma unroll
    for (int i = 0; i < 3; i++) { float d = tv[i] - mean; vs += d*d; }
    vs = blockReduceSum(vs);
    float rstd = rsqrtf(vs * (1.f / DDIM) + 1e-5f);
    #pragma unroll
    for (int i = 0; i < 3; i++) {
        int d = threadIdx.x + i*256;
        out[(size_t)t*DDIM + d] = xa[(size_t)t*DDIM + d] + (tv[i] - mean)*rstd*g[d] + b[d];
    }
}

// ---------------- launch ----------------
extern "C" void kernel_launch(void* const* d_in, const int* in_sizes, int n_in,
                              void* d_out, int out_size)
{
    const float* x        = (const float*)d_in[0];
    const float* ln_a_g   = (const float*)d_in[2];
    const float* ln_a_b   = (const float*)d_in[3];
    const float* wq       = (const float*)d_in[4];
    const float* bq       = (const float*)d_in[5];
    const float* wk       = (const float*)d_in[6];
    const float* bk       = (const float*)d_in[7];
    const float* wv       = (const float*)d_in[8];
    const float* bv       = (const float*)d_in[9];
    const float* wo       = (const float*)d_in[10];
    const float* bo       = (const float*)d_in[11];
    const float* ln_f_g   = (const float*)d_in[12];
    const float* ln_f_b   = (const float*)d_in[13];
    const float* gate_w   = (const float*)d_in[14];
    const float* gate_b   = (const float*)d_in[15];
    const float* w1       = (const float*)d_in[16];
    const float* b1       = (const float*)d_in[17];
    const float* w2       = (const float*)d_in[18];
    const float* b2       = (const float*)d_in[19];
    const float* moe_g    = (const float*)d_in[20];
    const float* moe_b    = (const float*)d_in[21];
    float* out = (float*)d_out;

    bf16 *a, *qb, *kb, *vb, *ctx, *hrb, *y1, *bwq, *bwk, *bwv, *bwo, *bw1, *bw2;
    float *xa, *h, *o2, *sc;
    int *cnt, *list;
    cudaGetSymbolAddress((void**)&a,   g_a);
    cudaGetSymbolAddress((void**)&qb,  g_q);
    cudaGetSymbolAddress((void**)&kb,  g_k);
    cudaGetSymbolAddress((void**)&vb,  g_v);
    cudaGetSymbolAddress((void**)&ctx, g_ctx);
    cudaGetSymbolAddress((void**)&xa,  g_xa);
    cudaGetSymbolAddress((void**)&h,   g_h);
    cudaGetSymbolAddress((void**)&hrb, g_hr);
    cudaGetSymbolAddress((void**)&y1,  g_y1);
    cudaGetSymbolAddress((void**)&o2,  g_o2);
    cudaGetSymbolAddress((void**)&sc,  g_sc);
    cudaGetSymbolAddress((void**)&cnt, g_cnt);
    cudaGetSymbolAddress((void**)&list,g_list);
    cudaGetSymbolAddress((void**)&bwq, g_bwq);
    cudaGetSymbolAddress((void**)&bwk, g_bwk);
    cudaGetSymbolAddress((void**)&bwv, g_bwv);
    cudaGetSymbolAddress((void**)&bwo, g_bwo);
    cudaGetSymbolAddress((void**)&bw1, g_bw1);
    cudaGetSymbolAddress((void**)&bw2, g_bw2);

    cudaFuncSetAttribute(bgemm_k<false,false,false,false,true,true>,
                         cudaFuncAttributeMaxDynamicSharedMemorySize, GSMEM);
    cudaFuncSetAttribute(bgemm_k<false,false,false,true,false,false>,
                         cudaFuncAttributeMaxDynamicSharedMemorySize, GSMEM);
    cudaFuncSetAttribute(bgemm_k<true,false,true,false,true,false>,
                         cudaFuncAttributeMaxDynamicSharedMemorySize, GSMEM);
    cudaFuncSetAttribute(bgemm_k<true,true,false,false,false,false>,
                         cudaFuncAttributeMaxDynamicSharedMemorySize, GSMEM);

    // 0) weight conversions f32 -> bf16
    {
        int nqkv4 = DDIM*DDIM/4;
        int gq = (nqkv4 + 255)/256;
        conv_bf16_kernel<<<gq, 256>>>(wq, bwq, nqkv4);
        conv_bf16_kernel<<<gq, 256>>>(wk, bwk, nqkv4);
        conv_bf16_kernel<<<gq, 256>>>(wv, bwv, nqkv4);
        conv_bf16_kernel<<<gq, 256>>>(wo, bwo, nqkv4);
        int nff4 = EE*DDIM*HID/4;
        int gf = (nff4 + 255)/256;
        conv_bf16_kernel<<<gf, 256>>>(w1, bw1, nff4);
        conv_bf16_kernel<<<gf, 256>>>(w2, bw2, nff4);
    }

    // 1) a = bf16(ln_attn(x))
    ln_kernel<1><<<NTOK, 256>>>(x, ln_a_g, ln_a_b, nullptr, a);

    // 2) fused q,k,v projections -> bf16 outputs
    dim3 gQKV(DDIM/128, NTOK/128, 3);
    bgemm_k<false,false,false,false,true,true><<<gQKV, 128, GSMEM>>>(
        NTOK, DDIM, DDIM, a, DDIM, bwq, bq, nullptr, (float*)qb, DDIM, nullptr, nullptr,
        bwk, bk, (float*)kb, bwv, bv, (float*)vb);

    // 3) tensor-core flash attention (causal), ctx bf16
    attn_tc_kernel<<<dim3(SS/64, HH, BB), 128>>>(qb, kb, vb, ctx);

    // 4) xa = x + ctx @ wo + bo
    dim3 gO(DDIM/128, NTOK/128, 1);
    bgemm_k<false,false,false,true,false,false><<<gO, 128, GSMEM>>>(
        NTOK, DDIM, DDIM, ctx, DDIM, bwo, bo, x, xa, DDIM, nullptr, nullptr,
        nullptr, nullptr, nullptr, nullptr, nullptr, nullptr);

    // 5) h = ln_ff(xa) (f32) + hr (bf16)
    ln_kernel<2><<<NTOK, 256>>>(xa, ln_f_g, ln_f_b, h, hrb);

    // 6) gate: top-2 per token + per-expert pair lists
    zero_cnt_kernel<<<1, 32>>>(cnt);
    gate_kernel<<<NTOK/8, 256>>>(h, gate_w, gate_b, sc, cnt, list);

    // 7) expert GEMM1: y1[pair] = bf16(relu(hr[token] @ w1[e] + b1[e]))
    bgemm_k<true,false,true,false,true,false><<<dim3(HID/128, CAP/128, EE), 128, GSMEM>>>(
        CAP, HID, DDIM, hrb, DDIM, bw1, b1, nullptr, (float*)y1, HID, list, cnt,
        nullptr, nullptr, nullptr, nullptr, nullptr, nullptr);

    // 8) expert GEMM2: o2[pair] = y1[pair] @ w2[e] + b2[e]
    bgemm_k<true,true,false,false,false,false><<<dim3(DDIM/128, CAP/128, EE), 128, GSMEM>>>(
        CAP, DDIM, HID, y1, HID, bw2, b2, nullptr, o2, DDIM, list, cnt,
        nullptr, nullptr, nullptr, nullptr, nullptr, nullptr);

    // 9) combine + post-LN + final residual
    combine_kernel<<<NTOK, 256>>>(h, o2, sc, xa, moe_g, moe_b, out);
}

// round 14
// speedup vs baseline: 1.3108x; 1.2741x over previous
#include <cuda_runtime.h>
#include <cuda_bf16.h>

#define BB 4
#define SS 1024
#define DDIM 768
#define HH 12
#define EE 8
#define HID 3072
#define DH 64
#define NTOK (BB*SS)
#define CAP (NTOK*2)

typedef __nv_bfloat16 bf16;
typedef __nv_bfloat162 bf162;

// ---------------- scratch ----------------
__device__ bf16  g_a[NTOK*DDIM];
__device__ bf16  g_q[NTOK*DDIM];
__device__ bf16  g_k[NTOK*DDIM];
__device__ bf16  g_v[NTOK*DDIM];
__device__ bf16  g_ctx[NTOK*DDIM];
__device__ float g_xa[NTOK*DDIM];
__device__ float g_h[NTOK*DDIM];
__device__ bf16  g_hr[NTOK*DDIM];
__device__ bf16  g_y1[CAP*HID];
__device__ float g_o2[CAP*DDIM];
__device__ float g_sc[CAP];
__device__ int   g_cnt[EE];
__device__ int   g_list[EE*CAP];
__device__ bf16  g_bwq[DDIM*DDIM];
__device__ bf16  g_bwk[DDIM*DDIM];
__device__ bf16  g_bwv[DDIM*DDIM];
__device__ bf16  g_bwo[DDIM*DDIM];
__device__ bf16  g_bw1[EE*DDIM*HID];
__device__ bf16  g_bw2[EE*HID*DDIM];

// ---------------- helpers ----------------
__device__ __forceinline__ unsigned smem_u32(const void* p) {
    return (unsigned)__cvta_generic_to_shared(p);
}
__device__ __forceinline__ void cp_async16(unsigned dst, const void* src, int srcsize) {
    asm volatile("cp.async.cg.shared.global [%0], [%1], 16, %2;"
                 :: "r"(dst), "l"(src), "r"(srcsize));
}
__device__ __forceinline__ void cp_commit() { asm volatile("cp.async.commit_group;"); }
template<int N>
__device__ __forceinline__ void cp_wait() { asm volatile("cp.async.wait_group %0;" :: "n"(N)); }

__device__ __forceinline__ void ldsm_x4(unsigned* r, unsigned addr) {
    asm volatile("ldmatrix.sync.aligned.m8n8.x4.shared.b16 {%0,%1,%2,%3}, [%4];"
        : "=r"(r[0]), "=r"(r[1]), "=r"(r[2]), "=r"(r[3]) : "r"(addr));
}
__device__ __forceinline__ void ldsm_x4_t(unsigned* r, unsigned addr) {
    asm volatile("ldmatrix.sync.aligned.m8n8.x4.trans.shared.b16 {%0,%1,%2,%3}, [%4];"
        : "=r"(r[0]), "=r"(r[1]), "=r"(r[2]), "=r"(r[3]) : "r"(addr));
}
__device__ __forceinline__ void mma_bf16(float c[4], const unsigned a[4],
                                         unsigned b0, unsigned b1) {
    asm volatile("mma.sync.aligned.m16n8k16.row.col.f32.bf16.bf16.f32 "
        "{%0,%1,%2,%3}, {%4,%5,%6,%7}, {%8,%9}, {%0,%1,%2,%3};"
        : "+f"(c[0]), "+f"(c[1]), "+f"(c[2]), "+f"(c[3])
        : "r"(a[0]), "r"(a[1]), "r"(a[2]), "r"(a[3]), "r"(b0), "r"(b1));
}
__device__ __forceinline__ unsigned pack_bf16(float a, float b) {
    bf162 t = __floats2bfloat162_rn(a, b);
    return *(unsigned*)&t;
}

__device__ __forceinline__ float blockReduceSum(float v) {
    __shared__ float sh[33];
    __syncthreads();
    int lane = threadIdx.x & 31, wid = threadIdx.x >> 5;
    #pragma unroll
    for (int o = 16; o > 0; o >>= 1) v += __shfl_down_sync(0xffffffffu, v, o);
    if (lane == 0) sh[wid] = v;
    __syncthreads();
    float r = (threadIdx.x < (blockDim.x >> 5)) ? sh[threadIdx.x] : 0.f;
    if (wid == 0) {
        #pragma unroll
        for (int o = 16; o > 0; o >>= 1) r += __shfl_down_sync(0xffffffffu, r, o);
        if (lane == 0) sh[32] = r;
    }
    __syncthreads();
    return sh[32];
}

// ---------------- weight conversion f32 -> bf16 ----------------
// 4 same-size tensors in one launch (grid.z selects), one float4 per thread.
__global__ void conv4_bf16_kernel(const float* __restrict__ s0, const float* __restrict__ s1,
                                  const float* __restrict__ s2, const float* __restrict__ s3,
                                  bf16* d0, bf16* d1, bf16* d2, bf16* d3, int n4) {
    const float* s; bf16* d;
    switch (blockIdx.z) {
        case 0: s = s0; d = d0; break;
        case 1: s = s1; d = d1; break;
        case 2: s = s2; d = d2; break;
        default: s = s3; d = d3; break;
    }
    int i = blockIdx.x * blockDim.x + threadIdx.x;
    if (i < n4) {
        float4 v = *(const float4*)(s + (size_t)i*4);
        bf162* dd = (bf162*)(d + (size_t)i*4);
        dd[0] = __floats2bfloat162_rn(v.x, v.y);
        dd[1] = __floats2bfloat162_rn(v.z, v.w);
    }
}

// Big conversion with ILP=4 (4 independent float4 loads in flight per thread).
__global__ void conv_bf16_ilp_kernel(const float* __restrict__ src, bf16* __restrict__ dst, int n4) {
    int base = blockIdx.x * (blockDim.x * 4) + threadIdx.x;
    float4 v[4];
    int idx[4];
    #pragma unroll
    for (int j = 0; j < 4; j++) {
        idx[j] = base + j * blockDim.x;
        if (idx[j] < n4) v[j] = *(const float4*)(src + (size_t)idx[j]*4);
    }
    #pragma unroll
    for (int j = 0; j < 4; j++) {
        if (idx[j] < n4) {
            bf162* d = (bf162*)(dst + (size_t)idx[j]*4);
            d[0] = __floats2bfloat162_rn(v[j].x, v[j].y);
            d[1] = __floats2bfloat162_rn(v[j].z, v[j].w);
        }
    }
}

// ---------------- layernorm ----------------
template<int MODE>
__global__ void ln_kernel(const float* __restrict__ x, const float* __restrict__ g,
                          const float* __restrict__ b, float* __restrict__ out,
                          bf16* __restrict__ out_b) {
    int row = blockIdx.x;
    const float* xr = x + (size_t)row * DDIM;
    float v[3];
    float s = 0.f;
    #pragma unroll
    for (int i = 0; i < 3; i++) { v[i] = xr[threadIdx.x + i*256]; s += v[i]; }
    s = blockReduceSum(s);
    float mean = s * (1.f / DDIM);
    float vs = 0.f;
    #pragma unroll
    for (int i = 0; i < 3; i++) { float d = v[i] - mean; vs += d*d; }
    vs = blockReduceSum(vs);
    float rstd = rsqrtf(vs * (1.f / DDIM) + 1e-5f);
    #pragma unroll
    for (int i = 0; i < 3; i++) {
        int d = threadIdx.x + i*256;
        float y = (v[i] - mean) * rstd * g[d] + b[d];
        if (MODE == 1) out_b[(size_t)row*DDIM + d] = __float2bfloat16_rn(y);
        if (MODE == 2) {
            out  [(size_t)row*DDIM + d] = y;
            out_b[(size_t)row*DDIM + d] = __float2bfloat16_rn(y);
        }
    }
}

// ---------------- bf16 tensor-core GEMM (R11 shape): 128x128 CTA, 8 warps 32x64 ----------------
#define ASTG 5120
#define BSTG 4352
#define ABYTES 10240
#define BBYTES 8704
#define GSMEM (4*(ABYTES + BBYTES) + 512)

template<bool GATHER, bool AROW_PAIR, bool RELU, bool RESID, bool OUTBF16, bool QKV3>
__global__ __launch_bounds__(256, 2) void bgemm_k(
    int M, int N, int K,
    const bf16* __restrict__ A, int lda,
    const bf16* __restrict__ Bm,
    const float* __restrict__ bias,
    const float* __restrict__ resid,
    float* __restrict__ C, int ldc,
    const int* __restrict__ rowlist,
    const int* __restrict__ cnt,
    const bf16* Bm2, const float* bias2, float* C2,
    const bf16* Bm3, const float* bias3, float* C3)
{
    extern __shared__ __align__(16) char smem_raw[];
    bf16* AsBase = (bf16*)smem_raw;
    bf16* BsBase = (bf16*)smem_raw + 4*ASTG;
    int*  rowsS  = (int*)(smem_raw + 4*(ABYTES + BBYTES));

    if (QKV3) {
        int z = blockIdx.z;
        if (z == 1) { Bm = Bm2; bias = bias2; C = C2; }
        else if (z == 2) { Bm = Bm3; bias = bias3; C = C3; }
    }
    if (GATHER) {
        int e = blockIdx.z;
        Bm      += (size_t)e * K * N;
        bias    += (size_t)e * N;
        rowlist += (size_t)e * CAP;
        cnt     += e;
    }
    int m0 = blockIdx.y * 128, n0 = blockIdx.x * 128;
    int tid = threadIdx.x, lane = tid & 31, wid = tid >> 5;
    int warpM = wid & 3, warpN = wid >> 2;

    if (GATHER) {
        int Meff = *cnt;
        if (m0 >= Meff) return;
        if (tid < 128) {
            int gidx = m0 + tid;
            rowsS[tid] = (gidx < Meff) ? rowlist[gidx] : -1;
        }
        __syncthreads();
    }

    int lm  = tid >> 1;
    int acb = (tid & 1) << 1;
    const bf16* Aptr;
    int asz = 16;
    if (GATHER) {
        int pr = rowsS[lm];
        if (pr < 0) { Aptr = A; asz = 0; }
        else Aptr = A + (size_t)(AROW_PAIR ? pr : (pr >> 1)) * lda + acb*8;
    } else {
        Aptr = A + (size_t)(m0 + lm) * lda + acb*8;
    }
    unsigned aD0 = smem_u32(&AsBase[lm*40]) + acb*16;

    int lbr = tid >> 3;
    int bcb = (tid & 7) << 1;
    const bf16* Bptr = Bm + (size_t)lbr * N + n0 + bcb*8;
    unsigned bD0 = smem_u32(&BsBase[lbr*136]) + bcb*16;

    int lane8 = lane & 7, laneH = lane & 8, laneK = (lane & 16) >> 1;
    unsigned aAddr[2], bAddr[4];
    #pragma unroll
    for (int mt = 0; mt < 2; mt++) {
        int r = warpM*32 + mt*16 + lane8 + laneH;
        aAddr[mt] = smem_u32(&AsBase[r*40 + laneK]);
    }
    #pragma unroll
    for (int ntp = 0; ntp < 4; ntp++) {
        int kr = lane8 + laneH;
        int nc = warpN*64 + ntp*16 + laneK;
        bAddr[ntp] = smem_u32(&BsBase[kr*136 + nc]);
    }

    float acc[2][8][4];
    #pragma unroll
    for (int i = 0; i < 2; i++)
        #pragma unroll
        for (int j = 0; j < 8; j++)
            #pragma unroll
            for (int q = 0; q < 4; q++) acc[i][j][q] = 0.f;

    auto issueStage = [&](int k0, int buf) {
        unsigned ad = aD0 + buf*ABYTES;
        cp_async16(ad,      Aptr + k0,     asz);
        cp_async16(ad + 16, Aptr + k0 + 8, asz);
        const bf16* bs = Bptr + (size_t)k0 * N;
        unsigned bd = bD0 + buf*BBYTES;
        cp_async16(bd,      bs,     16);
        cp_async16(bd + 16, bs + 8, 16);
        cp_commit();
    };

    int nStages = K >> 5;
    issueStage(0, 0);
    issueStage(32, 1);
    issueStage(64, 2);

    for (int s = 0; s < nStages; s++) {
        int rem = nStages - 1 - s;
        if (rem >= 2) cp_wait<2>();
        else if (rem == 1) cp_wait<1>();
        else cp_wait<0>();
        __syncthreads();
        if (s + 3 < nStages) issueStage((s + 3) << 5, (s + 3) & 3);

        int buf = s & 3;
        unsigned aOff = buf*ABYTES, bOff = buf*BBYTES;
        #pragma unroll
        for (int kk = 0; kk < 32; kk += 16) {
            unsigned af[2][4];
            ldsm_x4(af[0], aAddr[0] + aOff + kk*2);
            ldsm_x4(af[1], aAddr[1] + aOff + kk*2);
            #pragma unroll
            for (int ntp = 0; ntp < 4; ntp++) {
                unsigned bfr[4];
                ldsm_x4_t(bfr, bAddr[ntp] + bOff + kk*272);
                #pragma unroll
                for (int mt = 0; mt < 2; mt++) {
                    mma_bf16(acc[mt][ntp*2+0], af[mt], bfr[0], bfr[1]);
                    mma_bf16(acc[mt][ntp*2+1], af[mt], bfr[2], bfr[3]);
                }
            }
        }
    }

    #pragma unroll
    for (int mt = 0; mt < 2; mt++) {
        int rr0 = warpM*32 + mt*16 + (lane >> 2);
        #pragma unroll
        for (int half = 0; half < 2; half++) {
            int rloc = rr0 + half*8;
            int crow;
            if (GATHER) {
                int pr = rowsS[rloc];
                if (pr < 0) continue;
                crow = pr;
            } else {
                crow = m0 + rloc;
            }
            #pragma unroll
            for (int nt = 0; nt < 8; nt++) {
                int col = n0 + warpN*64 + nt*8 + (lane & 3)*2;
                float v0 = acc[mt][nt][half*2 + 0] + bias[col];
                float v1 = acc[mt][nt][half*2 + 1] + bias[col + 1];
                if (RELU) { v0 = fmaxf(v0, 0.f); v1 = fmaxf(v1, 0.f); }
                if (RESID) {
                    const float* rp = resid + (size_t)crow*ldc + col;
                    v0 += rp[0]; v1 += rp[1];
                }
                if (OUTBF16) {
                    *(bf162*)((bf16*)C + (size_t)crow*ldc + col) =
                        __floats2bfloat162_rn(v0, v1);
                } else {
                    *(float2*)(C + (size_t)crow*ldc + col) = make_float2(v0, v1);
                }
            }
        }
    }
}

// ---------------- tensor-core flash attention (causal, bf16 mma) ----------------
#define ATS 72

__global__ void __launch_bounds__(128) attn_tc_kernel(
    const bf16* __restrict__ q, const bf16* __restrict__ k,
    const bf16* __restrict__ v, bf16* __restrict__ ctx)
{
    __shared__ __align__(16) bf16 Qs[64*ATS];
    __shared__ __align__(16) bf16 Ks[2][64*ATS];
    __shared__ __align__(16) bf16 Vs[2][64*ATS];

    // longest causal tiles first (scheduler picks low blockIdx first)
    int qt = gridDim.x - 1 - blockIdx.x;
    int h = blockIdx.y, b = blockIdx.z;
    int q0 = qt * 64;
    int tid = threadIdx.x, lane = tid & 31, w = tid >> 5;

    int srow = tid >> 1;
    int sc0  = (tid & 1) * 4;
    const bf16* qg = q + (size_t)(b*SS + q0 + srow)*DDIM + h*DH + sc0*8;
    unsigned qDst = smem_u32(&Qs[srow*ATS]) + sc0*16;
    unsigned kDst = smem_u32(&Ks[0][srow*ATS]) + sc0*16;
    unsigned vDst = smem_u32(&Vs[0][srow*ATS]) + sc0*16;
    const bf16* kg0 = k + (size_t)(b*SS + srow)*DDIM + h*DH + sc0*8;
    const bf16* vg0 = v + (size_t)(b*SS + srow)*DDIM + h*DH + sc0*8;

    auto issueKV = [&](int kt, int buf) {
        unsigned kd = kDst + buf*(64*ATS*2);
        unsigned vd = vDst + buf*(64*ATS*2);
        const bf16* kgp = kg0 + (size_t)kt*DDIM;
        const bf16* vgp = vg0 + (size_t)kt*DDIM;
        #pragma unroll
        for (int j = 0; j < 4; j++) {
            cp_async16(kd + j*16, kgp + j*8, 16);
            cp_async16(vd + j*16, vgp + j*8, 16);
        }
        cp_commit();
    };

    #pragma unroll
    for (int j = 0; j < 4; j++) cp_async16(qDst + j*16, qg + j*8, 16);
    issueKV(0, 0);

    int l15 = lane & 15;
    int lH8 = (lane >> 4) << 3;
    int lB8 = ((lane >> 3) & 1) << 3;
    int bRowP = lH8 + (lane & 7);

    unsigned qf[4][4];
    float m0 = -1e30f, m1 = -1e30f, l0 = 0.f, l1 = 0.f;
    float oa[8][4];
    #pragma unroll
    for (int j = 0; j < 8; j++)
        #pragma unroll
        for (int e = 0; e < 4; e++) oa[j][e] = 0.f;

    int r0loc = lane >> 2;
    int rowg0 = q0 + 16*w + r0loc;
    int rowg1 = rowg0 + 8;
    int c2 = (lane & 3) * 2;

    int nt = q0/64 + 1;
    for (int t = 0; t < nt; t++) {
        cp_wait<0>();
        __syncthreads();
        if (t == 0) {
            #pragma unroll
            for (int kk = 0; kk < 4; kk++)
                ldsm_x4(qf[kk], smem_u32(&Qs[(16*w + l15)*ATS + kk*16 + lH8]));
        }
        if (t + 1 < nt) issueKV((t+1)*64, (t+1) & 1);

        int buf = t & 1;
        int kt = t * 64;
        const bf16* KsB = Ks[buf];
        const bf16* VsB = Vs[buf];

        float sf[8][4];
        #pragma unroll
        for (int j = 0; j < 8; j++)
            #pragma unroll
            for (int e = 0; e < 4; e++) sf[j][e] = 0.f;
        #pragma unroll
        for (int kk = 0; kk < 4; kk++) {
            #pragma unroll
            for (int j2 = 0; j2 < 4; j2++) {
                unsigned bk[4];
                ldsm_x4(bk, smem_u32(&KsB[(16*j2 + bRowP)*ATS + kk*16 + lB8]));
                mma_bf16(sf[2*j2+0], qf[kk], bk[0], bk[1]);
                mma_bf16(sf[2*j2+1], qf[kk], bk[2], bk[3]);
            }
        }
        #pragma unroll
        for (int j = 0; j < 8; j++)
            #pragma unroll
            for (int e = 0; e < 4; e++) sf[j][e] *= 0.125f;
        if (kt == q0) {
            #pragma unroll
            for (int j = 0; j < 8; j++) {
                int col = kt + 8*j + c2;
                if (col     > rowg0) sf[j][0] = -1e30f;
                if (col + 1 > rowg0) sf[j][1] = -1e30f;
                if (col     > rowg1) sf[j][2] = -1e30f;
                if (col + 1 > rowg1) sf[j][3] = -1e30f;
            }
        }
        float tm0 = -1e30f, tm1 = -1e30f;
        #pragma unroll
        for (int j = 0; j < 8; j++) {
            tm0 = fmaxf(tm0, fmaxf(sf[j][0], sf[j][1]));
            tm1 = fmaxf(tm1, fmaxf(sf[j][2], sf[j][3]));
        }
        tm0 = fmaxf(tm0, __shfl_xor_sync(0xffffffffu, tm0, 1));
        tm0 = fmaxf(tm0, __shfl_xor_sync(0xffffffffu, tm0, 2));
        tm1 = fmaxf(tm1, __shfl_xor_sync(0xffffffffu, tm1, 1));
        tm1 = fmaxf(tm1, __shfl_xor_sync(0xffffffffu, tm1, 2));
        float nm0 = fmaxf(m0, tm0), nm1 = fmaxf(m1, tm1);
        float cc0 = __expf(m0 - nm0), cc1 = __expf(m1 - nm1);
        l0 *= cc0; l1 *= cc1;
        #pragma unroll
        for (int j = 0; j < 8; j++) {
            oa[j][0] *= cc0; oa[j][1] *= cc0;
            oa[j][2] *= cc1; oa[j][3] *= cc1;
        }
        float ps0 = 0.f, ps1 = 0.f;
        #pragma unroll
        for (int j = 0; j < 8; j++) {
            sf[j][0] = __expf(sf[j][0] - nm0);
            sf[j][1] = __expf(sf[j][1] - nm0);
            sf[j][2] = __expf(sf[j][2] - nm1);
            sf[j][3] = __expf(sf[j][3] - nm1);
            ps0 += sf[j][0] + sf[j][1];
            ps1 += sf[j][2] + sf[j][3];
        }
        l0 += ps0; l1 += ps1; m0 = nm0; m1 = nm1;

        unsigned pf[4][4];
        #pragma unroll
        for (int t2 = 0; t2 < 4; t2++) {
            pf[t2][0] = pack_bf16(sf[2*t2][0],   sf[2*t2][1]);
            pf[t2][1] = pack_bf16(sf[2*t2][2],   sf[2*t2][3]);
            pf[t2][2] = pack_bf16(sf[2*t2+1][0], sf[2*t2+1][1]);
            pf[t2][3] = pack_bf16(sf[2*t2+1][2], sf[2*t2+1][3]);
        }
        #pragma unroll
        for (int t2 = 0; t2 < 4; t2++) {
            #pragma unroll
            for (int g = 0; g < 4; g++) {
                unsigned bv[4];
                ldsm_x4_t(bv, smem_u32(&VsB[(16*t2 + l15)*ATS + 16*g + lH8]));
                mma_bf16(oa[2*g+0], pf[t2], bv[0], bv[1]);
                mma_bf16(oa[2*g+1], pf[t2], bv[2], bv[3]);
            }
        }
        __syncthreads();
    }

    l0 += __shfl_xor_sync(0xffffffffu, l0, 1);
    l0 += __shfl_xor_sync(0xffffffffu, l0, 2);
    l1 += __shfl_xor_sync(0xffffffffu, l1, 1);
    l1 += __shfl_xor_sync(0xffffffffu, l1, 2);
    float inv0 = 1.f / l0, inv1 = 1.f / l1;

    bf16* c0p = ctx + (size_t)(b*SS + rowg0)*DDIM + h*DH + c2;
    bf16* c1p = ctx + (size_t)(b*SS + rowg1)*DDIM + h*DH + c2;
    #pragma unroll
    for (int j = 0; j < 8; j++) {
        *(bf162*)(c0p + 8*j) = __floats2bfloat162_rn(oa[j][0]*inv0, oa[j][1]*inv0);
        *(bf162*)(c1p + 8*j) = __floats2bfloat162_rn(oa[j][2]*inv1, oa[j][3]*inv1);
    }
}

// ---------------- gate ----------------
__global__ void zero_cnt_kernel(int* cnt) {
    if (threadIdx.x < EE) cnt[threadIdx.x] = 0;
}

__global__ void gate_kernel(const float* __restrict__ h, const float* __restrict__ gw,
                            const float* __restrict__ gb, float* __restrict__ sc,
                            int* __restrict__ cnt, int* __restrict__ list)
{
    int warp = (blockIdx.x * blockDim.x + threadIdx.x) >> 5;
    if (warp >= NTOK) return;
    int lane = threadIdx.x & 31;
    float a[8] = {0,0,0,0,0,0,0,0};
    const float* hr = h + (size_t)warp * DDIM;
    for (int d = lane; d < DDIM; d += 32) {
        float hv = hr[d];
        float4 w0 = *(const float4*)(gw + (size_t)d*EE);
        float4 w1 = *(const float4*)(gw + (size_t)d*EE + 4);
        a[0]+=hv*w0.x; a[1]+=hv*w0.y; a[2]+=hv*w0.z; a[3]+=hv*w0.w;
        a[4]+=hv*w1.x; a[5]+=hv*w1.y; a[6]+=hv*w1.z; a[7]+=hv*w1.w;
    }
    #pragma unroll
    for (int e = 0; e < 8; e++)
        #pragma unroll
        for (int o = 16; o > 0; o >>= 1)
            a[e] += __shfl_down_sync(0xffffffffu, a[e], o);
    if (lane == 0) {
        float lg[8];
        #pragma unroll
        for (int e = 0; e < 8; e++) lg[e] = a[e] + gb[e];
        int i0 = 0; float v0 = lg[0];
        #pragma unroll
        for (int e = 1; e < 8; e++) if (lg[e] > v0) { v0 = lg[e]; i0 = e; }
        int i1 = -1; float v1 = -3.0e38f;
        #pragma unroll
        for (int e = 0; e < 8; e++) if (e != i0 && lg[e] > v1) { v1 = lg[e]; i1 = e; }
        float e1 = __expf(v1 - v0);
        float s0 = 1.f / (1.f + e1);
        float s1 = e1 * s0;
        sc[2*warp]   = s0;
        sc[2*warp+1] = s1;
        int p0 = atomicAdd(&cnt[i0], 1);
        list[(size_t)i0*CAP + p0] = 2*warp;
        int p1 = atomicAdd(&cnt[i1], 1);
        list[(size_t)i1*CAP + p1] = 2*warp + 1;
    }
}

// ---------------- combine ----------------
__global__ void combine_kernel(const float* __restrict__ h, const float* __restrict__ o2,
                               const float* __restrict__ sc, const float* __restrict__ xa,
                               const float* __restrict__ g, const float* __restrict__ b,
                               float* __restrict__ out)
{
    int t = blockIdx.x;
    const float* hr = h + (size_t)t*DDIM;
    const float* r0 = o2 + (size_t)(2*t)*DDIM;
    const float* r1 = o2 + (size_t)(2*t+1)*DDIM;
    float s0 = sc[2*t], s1 = sc[2*t+1];
    float tv[3];
    float s = 0.f;
    #pragma unroll
    for (int i = 0; i < 3; i++) {
        int d = threadIdx.x + i*256;
        tv[i] = hr[d] + s0*r0[d] + s1*r1[d];
        s += tv[i];
    }
    s = blockReduceSum(s);
    float mean = s * (1.f / DDIM);
    float vs = 0.f;
    #pragma unroll
    for (int i = 0; i < 3; i++) { float d = tv[i] - mean; vs += d*d; }
    vs = blockReduceSum(vs);
    float rstd = rsqrtf(vs * (1.f / DDIM) + 1e-5f);
    #pragma unroll
    for (int i = 0; i < 3; i++) {
        int d = threadIdx.x + i*256;
        out[(size_t)t*DDIM + d] = xa[(size_t)t*DDIM + d] + (tv[i] - mean)*rstd*g[d] + b[d];
    }
}

// ---------------- launch ----------------
extern "C" void kernel_launch(void* const* d_in, const int* in_sizes, int n_in,
                              void* d_out, int out_size)
{
    const float* x        = (const float*)d_in[0];
    const float* ln_a_g   = (const float*)d_in[2];
    const float* ln_a_b   = (const float*)d_in[3];
    const float* wq       = (const float*)d_in[4];
    const float* bq       = (const float*)d_in[5];
    const float* wk       = (const float*)d_in[6];
    const float* bk       = (const float*)d_in[7];
    const float* wv       = (const float*)d_in[8];
    const float* bv       = (const float*)d_in[9];
    const float* wo       = (const float*)d_in[10];
    const float* bo       = (const float*)d_in[11];
    const float* ln_f_g   = (const float*)d_in[12];
    const float* ln_f_b   = (const float*)d_in[13];
    const float* gate_w   = (const float*)d_in[14];
    const float* gate_b   = (const float*)d_in[15];
    const float* w1       = (const float*)d_in[16];
    const float* b1       = (const float*)d_in[17];
    const float* w2       = (const float*)d_in[18];
    const float* b2       = (const float*)d_in[19];
    const float* moe_g    = (const float*)d_in[20];
    const float* moe_b    = (const float*)d_in[21];
    float* out = (float*)d_out;

    bf16 *a, *qb, *kb, *vb, *ctx, *hrb, *y1, *bwq, *bwk, *bwv, *bwo, *bw1, *bw2;
    float *xa, *h, *o2, *sc;
    int *cnt, *list;
    cudaGetSymbolAddress((void**)&a,   g_a);
    cudaGetSymbolAddress((void**)&qb,  g_q);
    cudaGetSymbolAddress((void**)&kb,  g_k);
    cudaGetSymbolAddress((void**)&vb,  g_v);
    cudaGetSymbolAddress((void**)&ctx, g_ctx);
    cudaGetSymbolAddress((void**)&xa,  g_xa);
    cudaGetSymbolAddress((void**)&h,   g_h);
    cudaGetSymbolAddress((void**)&hrb, g_hr);
    cudaGetSymbolAddress((void**)&y1,  g_y1);
    cudaGetSymbolAddress((void**)&o2,  g_o2);
    cudaGetSymbolAddress((void**)&sc,  g_sc);
    cudaGetSymbolAddress((void**)&cnt, g_cnt);
    cudaGetSymbolAddress((void**)&list,g_list);
    cudaGetSymbolAddress((void**)&bwq, g_bwq);
    cudaGetSymbolAddress((void**)&bwk, g_bwk);
    cudaGetSymbolAddress((void**)&bwv, g_bwv);
    cudaGetSymbolAddress((void**)&bwo, g_bwo);
    cudaGetSymbolAddress((void**)&bw1, g_bw1);
    cudaGetSymbolAddress((void**)&bw2, g_bw2);

    cudaFuncSetAttribute(bgemm_k<false,false,false,false,true,true>,
                         cudaFuncAttributeMaxDynamicSharedMemorySize, GSMEM);
    cudaFuncSetAttribute(bgemm_k<false,false,false,true,false,false>,
                         cudaFuncAttributeMaxDynamicSharedMemorySize, GSMEM);
    cudaFuncSetAttribute(bgemm_k<true,false,true,false,true,false>,
                         cudaFuncAttributeMaxDynamicSharedMemorySize, GSMEM);
    cudaFuncSetAttribute(bgemm_k<true,true,false,false,false,false>,
                         cudaFuncAttributeMaxDynamicSharedMemorySize, GSMEM);

    // 0) weight conversions f32 -> bf16
    {
        int nqkv4 = DDIM*DDIM/4;                       // 147456
        conv4_bf16_kernel<<<dim3((nqkv4 + 255)/256, 1, 4), 256>>>(
            wq, wk, wv, wo, bwq, bwk, bwv, bwo, nqkv4);
        int nff4 = EE*DDIM*HID/4;                      // 4718592
        int gf = (nff4 + 1023)/1024;                   // ILP=4 per thread
        conv_bf16_ilp_kernel<<<gf, 256>>>(w1, bw1, nff4);
        conv_bf16_ilp_kernel<<<gf, 256>>>(w2, bw2, nff4);
    }

    // 1) a = bf16(ln_attn(x))
    ln_kernel<1><<<NTOK, 256>>>(x, ln_a_g, ln_a_b, nullptr, a);

    // 2) fused q,k,v projections -> bf16 outputs
    dim3 gQKV(DDIM/128, NTOK/128, 3);
    bgemm_k<false,false,false,false,true,true><<<gQKV, 256, GSMEM>>>(
        NTOK, DDIM, DDIM, a, DDIM, bwq, bq, nullptr, (float*)qb, DDIM, nullptr, nullptr,
        bwk, bk, (float*)kb, bwv, bv, (float*)vb);

    // 3) tensor-core flash attention (causal), ctx bf16
    attn_tc_kernel<<<dim3(SS/64, HH, BB), 128>>>(qb, kb, vb, ctx);

    // 4) xa = x + ctx @ wo + bo
    dim3 gO(DDIM/128, NTOK/128, 1);
    bgemm_k<false,false,false,true,false,false><<<gO, 256, GSMEM>>>(
        NTOK, DDIM, DDIM, ctx, DDIM, bwo, bo, x, xa, DDIM, nullptr, nullptr,
        nullptr, nullptr, nullptr, nullptr, nullptr, nullptr);

    // 5) h = ln_ff(xa) (f32) + hr (bf16)
    ln_kernel<2><<<NTOK, 256>>>(xa, ln_f_g, ln_f_b, h, hrb);

    // 6) gate: top-2 per token + per-expert pair lists
    zero_cnt_kernel<<<1, 32>>>(cnt);
    gate_kernel<<<NTOK/8, 256>>>(h, gate_w, gate_b, sc, cnt, list);

    // 7) expert GEMM1: y1[pair] = bf16(relu(hr[token] @ w1[e] + b1[e]))
    bgemm_k<true,false,true,false,true,false><<<dim3(HID/128, CAP/128, EE), 256, GSMEM>>>(
        CAP, HID, DDIM, hrb, DDIM, bw1, b1, nullptr, (float*)y1, HID, list, cnt,
        nullptr, nullptr, nullptr, nullptr, nullptr, nullptr);

    // 8) expert GEMM2: o2[pair] = y1[pair] @ w2[e] + b2[e]
    bgemm_k<true,true,false,false,false,false><<<dim3(DDIM/128, CAP/128, EE), 256, GSMEM>>>(
        CAP, DDIM, HID, y1, HID, bw2, b2, nullptr, o2, DDIM, list, cnt,
        nullptr, nullptr, nullptr, nullptr, nullptr, nullptr);

    // 9) combine + post-LN + final residual
    combine_kernel<<<NTOK, 256>>>(h, o2, sc, xa, moe_g, moe_b, out);
}

// round 15
// speedup vs baseline: 1.3219x; 1.0084x over previous
#include <cuda_runtime.h>
#include <cuda_bf16.h>

#define BB 4
#define SS 1024
#define DDIM 768
#define HH 12
#define EE 8
#define HID 3072
#define DH 64
#define NTOK (BB*SS)
#define CAP (NTOK*2)

typedef __nv_bfloat16 bf16;
typedef __nv_bfloat162 bf162;

// ---------------- scratch ----------------
__device__ bf16  g_a[NTOK*DDIM];
__device__ bf16  g_q[NTOK*DDIM];
__device__ bf16  g_k[NTOK*DDIM];
__device__ bf16  g_v[NTOK*DDIM];
__device__ bf16  g_ctx[NTOK*DDIM];
__device__ float g_xa[NTOK*DDIM];
__device__ float g_h[NTOK*DDIM];
__device__ bf16  g_hr[NTOK*DDIM];
__device__ bf16  g_y1[CAP*HID];
__device__ float g_o2[CAP*DDIM];
__device__ float g_sc[CAP];
__device__ int   g_cnt[EE];
__device__ int   g_list[EE*CAP];
__device__ bf16  g_bwq[DDIM*DDIM];
__device__ bf16  g_bwk[DDIM*DDIM];
__device__ bf16  g_bwv[DDIM*DDIM];
__device__ bf16  g_bwo[DDIM*DDIM];
__device__ bf16  g_bw1[EE*DDIM*HID];
__device__ bf16  g_bw2[EE*HID*DDIM];

// ---------------- helpers ----------------
__device__ __forceinline__ unsigned smem_u32(const void* p) {
    return (unsigned)__cvta_generic_to_shared(p);
}
__device__ __forceinline__ void cp_async16(unsigned dst, const void* src, int srcsize) {
    asm volatile("cp.async.cg.shared.global [%0], [%1], 16, %2;"
                 :: "r"(dst), "l"(src), "r"(srcsize));
}
__device__ __forceinline__ void cp_commit() { asm volatile("cp.async.commit_group;"); }
template<int N>
__device__ __forceinline__ void cp_wait() { asm volatile("cp.async.wait_group %0;" :: "n"(N)); }

__device__ __forceinline__ void ldsm_x4(unsigned* r, unsigned addr) {
    asm volatile("ldmatrix.sync.aligned.m8n8.x4.shared.b16 {%0,%1,%2,%3}, [%4];"
        : "=r"(r[0]), "=r"(r[1]), "=r"(r[2]), "=r"(r[3]) : "r"(addr));
}
__device__ __forceinline__ void ldsm_x4_t(unsigned* r, unsigned addr) {
    asm volatile("ldmatrix.sync.aligned.m8n8.x4.trans.shared.b16 {%0,%1,%2,%3}, [%4];"
        : "=r"(r[0]), "=r"(r[1]), "=r"(r[2]), "=r"(r[3]) : "r"(addr));
}
__device__ __forceinline__ void mma_bf16(float c[4], const unsigned a[4],
                                         unsigned b0, unsigned b1) {
    asm volatile("mma.sync.aligned.m16n8k16.row.col.f32.bf16.bf16.f32 "
        "{%0,%1,%2,%3}, {%4,%5,%6,%7}, {%8,%9}, {%0,%1,%2,%3};"
        : "+f"(c[0]), "+f"(c[1]), "+f"(c[2]), "+f"(c[3])
        : "r"(a[0]), "r"(a[1]), "r"(a[2]), "r"(a[3]), "r"(b0), "r"(b1));
}
__device__ __forceinline__ unsigned pack_bf16(float a, float b) {
    bf162 t = __floats2bfloat162_rn(a, b);
    return *(unsigned*)&t;
}

// ---------------- weight conversion f32 -> bf16 ----------------
__global__ void conv4_bf16_kernel(const float* __restrict__ s0, const float* __restrict__ s1,
                                  const float* __restrict__ s2, const float* __restrict__ s3,
                                  bf16* d0, bf16* d1, bf16* d2, bf16* d3, int n4) {
    const float* s; bf16* d;
    switch (blockIdx.z) {
        case 0: s = s0; d = d0; break;
        case 1: s = s1; d = d1; break;
        case 2: s = s2; d = d2; break;
        default: s = s3; d = d3; break;
    }
    int i = blockIdx.x * blockDim.x + threadIdx.x;
    if (i < n4) {
        float4 v = *(const float4*)(s + (size_t)i*4);
        bf162* dd = (bf162*)(d + (size_t)i*4);
        dd[0] = __floats2bfloat162_rn(v.x, v.y);
        dd[1] = __floats2bfloat162_rn(v.z, v.w);
    }
}

__global__ void conv_bf16_ilp_kernel(const float* __restrict__ src, bf16* __restrict__ dst, int n4) {
    int base = blockIdx.x * (blockDim.x * 4) + threadIdx.x;
    float4 v[4];
    int idx[4];
    #pragma unroll
    for (int j = 0; j < 4; j++) {
        idx[j] = base + j * blockDim.x;
        if (idx[j] < n4) v[j] = *(const float4*)(src + (size_t)idx[j]*4);
    }
    #pragma unroll
    for (int j = 0; j < 4; j++) {
        if (idx[j] < n4) {
            bf162* d = (bf162*)(dst + (size_t)idx[j]*4);
            d[0] = __floats2bfloat162_rn(v[j].x, v[j].y);
            d[1] = __floats2bfloat162_rn(v[j].z, v[j].w);
        }
    }
}

// ---------------- layernorm: warp-per-row (no barriers, no smem) ----------------
// 768 = 32 lanes * 6 float4. 8 rows per 256-thread block.
template<int MODE>
__global__ void ln_kernel(const float* __restrict__ x, const float* __restrict__ g,
                          const float* __restrict__ b, float* __restrict__ out,
                          bf16* __restrict__ out_b) {
    int wid = threadIdx.x >> 5, lane = threadIdx.x & 31;
    int row = blockIdx.x * 8 + wid;
    const float* xr = x + (size_t)row * DDIM;

    float4 v[6];
    float s = 0.f;
    #pragma unroll
    for (int j = 0; j < 6; j++) {
        v[j] = *(const float4*)(xr + lane*4 + j*128);
        s += (v[j].x + v[j].y) + (v[j].z + v[j].w);
    }
    #pragma unroll
    for (int o = 16; o > 0; o >>= 1) s += __shfl_xor_sync(0xffffffffu, s, o);
    float mean = s * (1.f / DDIM);

    float vs = 0.f;
    #pragma unroll
    for (int j = 0; j < 6; j++) {
        float a0 = v[j].x - mean, a1 = v[j].y - mean;
        float a2 = v[j].z - mean, a3 = v[j].w - mean;
        vs += (a0*a0 + a1*a1) + (a2*a2 + a3*a3);
    }
    #pragma unroll
    for (int o = 16; o > 0; o >>= 1) vs += __shfl_xor_sync(0xffffffffu, vs, o);
    float rstd = rsqrtf(vs * (1.f / DDIM) + 1e-5f);

    #pragma unroll
    for (int j = 0; j < 6; j++) {
        int d = lane*4 + j*128;
        float4 gg = *(const float4*)(g + d);
        float4 bb = *(const float4*)(b + d);
        float y0 = (v[j].x - mean)*rstd*gg.x + bb.x;
        float y1 = (v[j].y - mean)*rstd*gg.y + bb.y;
        float y2 = (v[j].z - mean)*rstd*gg.z + bb.z;
        float y3 = (v[j].w - mean)*rstd*gg.w + bb.w;
        bf162 p0 = __floats2bfloat162_rn(y0, y1);
        bf162 p1 = __floats2bfloat162_rn(y2, y3);
        uint2 pk = make_uint2(*(unsigned*)&p0, *(unsigned*)&p1);
        *(uint2*)(out_b + (size_t)row*DDIM + d) = pk;
        if (MODE == 2)
            *(float4*)(out + (size_t)row*DDIM + d) = make_float4(y0, y1, y2, y3);
    }
}

// ---------------- bf16 tensor-core GEMM (R11 shape): 128x128 CTA, 8 warps 32x64 ----------------
#define ASTG 5120
#define BSTG 4352
#define ABYTES 10240
#define BBYTES 8704
#define GSMEM (4*(ABYTES + BBYTES) + 512)

template<bool GATHER, bool AROW_PAIR, bool RELU, bool RESID, bool OUTBF16, bool QKV3>
__global__ __launch_bounds__(256, 2) void bgemm_k(
    int M, int N, int K,
    const bf16* __restrict__ A, int lda,
    const bf16* __restrict__ Bm,
    const float* __restrict__ bias,
    const float* __restrict__ resid,
    float* __restrict__ C, int ldc,
    const int* __restrict__ rowlist,
    const int* __restrict__ cnt,
    const bf16* Bm2, const float* bias2, float* C2,
    const bf16* Bm3, const float* bias3, float* C3)
{
    extern __shared__ __align__(16) char smem_raw[];
    bf16* AsBase = (bf16*)smem_raw;
    bf16* BsBase = (bf16*)smem_raw + 4*ASTG;
    int*  rowsS  = (int*)(smem_raw + 4*(ABYTES + BBYTES));

    if (QKV3) {
        int z = blockIdx.z;
        if (z == 1) { Bm = Bm2; bias = bias2; C = C2; }
        else if (z == 2) { Bm = Bm3; bias = bias3; C = C3; }
    }
    if (GATHER) {
        int e = blockIdx.z;
        Bm      += (size_t)e * K * N;
        bias    += (size_t)e * N;
        rowlist += (size_t)e * CAP;
        cnt     += e;
    }
    int m0 = blockIdx.y * 128, n0 = blockIdx.x * 128;
    int tid = threadIdx.x, lane = tid & 31, wid = tid >> 5;
    int warpM = wid & 3, warpN = wid >> 2;

    if (GATHER) {
        int Meff = *cnt;
        if (m0 >= Meff) return;
        if (tid < 128) {
            int gidx = m0 + tid;
            rowsS[tid] = (gidx < Meff) ? rowlist[gidx] : -1;
        }
        __syncthreads();
    }

    int lm  = tid >> 1;
    int acb = (tid & 1) << 1;
    const bf16* Aptr;
    int asz = 16;
    if (GATHER) {
        int pr = rowsS[lm];
        if (pr < 0) { Aptr = A; asz = 0; }
        else Aptr = A + (size_t)(AROW_PAIR ? pr : (pr >> 1)) * lda + acb*8;
    } else {
        Aptr = A + (size_t)(m0 + lm) * lda + acb*8;
    }
    unsigned aD0 = smem_u32(&AsBase[lm*40]) + acb*16;

    int lbr = tid >> 3;
    int bcb = (tid & 7) << 1;
    const bf16* Bptr = Bm + (size_t)lbr * N + n0 + bcb*8;
    unsigned bD0 = smem_u32(&BsBase[lbr*136]) + bcb*16;

    int lane8 = lane & 7, laneH = lane & 8, laneK = (lane & 16) >> 1;
    unsigned aAddr[2], bAddr[4];
    #pragma unroll
    for (int mt = 0; mt < 2; mt++) {
        int r = warpM*32 + mt*16 + lane8 + laneH;
        aAddr[mt] = smem_u32(&AsBase[r*40 + laneK]);
    }
    #pragma unroll
    for (int ntp = 0; ntp < 4; ntp++) {
        int kr = lane8 + laneH;
        int nc = warpN*64 + ntp*16 + laneK;
        bAddr[ntp] = smem_u32(&BsBase[kr*136 + nc]);
    }

    float acc[2][8][4];
    #pragma unroll
    for (int i = 0; i < 2; i++)
        #pragma unroll
        for (int j = 0; j < 8; j++)
            #pragma unroll
            for (int q = 0; q < 4; q++) acc[i][j][q] = 0.f;

    auto issueStage = [&](int k0, int buf) {
        unsigned ad = aD0 + buf*ABYTES;
        cp_async16(ad,      Aptr + k0,     asz);
        cp_async16(ad + 16, Aptr + k0 + 8, asz);
        const bf16* bs = Bptr + (size_t)k0 * N;
        unsigned bd = bD0 + buf*BBYTES;
        cp_async16(bd,      bs,     16);
        cp_async16(bd + 16, bs + 8, 16);
        cp_commit();
    };

    int nStages = K >> 5;
    issueStage(0, 0);
    issueStage(32, 1);
    issueStage(64, 2);

    for (int s = 0; s < nStages; s++) {
        int rem = nStages - 1 - s;
        if (rem >= 2) cp_wait<2>();
        else if (rem == 1) cp_wait<1>();
        else cp_wait<0>();
        __syncthreads();
        if (s + 3 < nStages) issueStage((s + 3) << 5, (s + 3) & 3);

        int buf = s & 3;
        unsigned aOff = buf*ABYTES, bOff = buf*BBYTES;
        #pragma unroll
        for (int kk = 0; kk < 32; kk += 16) {
            unsigned af[2][4];
            ldsm_x4(af[0], aAddr[0] + aOff + kk*2);
            ldsm_x4(af[1], aAddr[1] + aOff + kk*2);
            #pragma unroll
            for (int ntp = 0; ntp < 4; ntp++) {
                unsigned bfr[4];
                ldsm_x4_t(bfr, bAddr[ntp] + bOff + kk*272);
                #pragma unroll
                for (int mt = 0; mt < 2; mt++) {
                    mma_bf16(acc[mt][ntp*2+0], af[mt], bfr[0], bfr[1]);
                    mma_bf16(acc[mt][ntp*2+1], af[mt], bfr[2], bfr[3]);
                }
            }
        }
    }

    #pragma unroll
    for (int mt = 0; mt < 2; mt++) {
        int rr0 = warpM*32 + mt*16 + (lane >> 2);
        #pragma unroll
        for (int half = 0; half < 2; half++) {
            int rloc = rr0 + half*8;
            int crow;
            if (GATHER) {
                int pr = rowsS[rloc];
                if (pr < 0) continue;
                crow = pr;
            } else {
                crow = m0 + rloc;
            }
            #pragma unroll
            for (int nt = 0; nt < 8; nt++) {
                int col = n0 + warpN*64 + nt*8 + (lane & 3)*2;
                float v0 = acc[mt][nt][half*2 + 0] + bias[col];
                float v1 = acc[mt][nt][half*2 + 1] + bias[col + 1];
                if (RELU) { v0 = fmaxf(v0, 0.f); v1 = fmaxf(v1, 0.f); }
                if (RESID) {
                    const float* rp = resid + (size_t)crow*ldc + col;
                    v0 += rp[0]; v1 += rp[1];
                }
                if (OUTBF16) {
                    *(bf162*)((bf16*)C + (size_t)crow*ldc + col) =
                        __floats2bfloat162_rn(v0, v1);
                } else {
                    *(float2*)(C + (size_t)crow*ldc + col) = make_float2(v0, v1);
                }
            }
        }
    }
}

// ---------------- tensor-core flash attention (causal, bf16 mma) ----------------
#define ATS 72

__global__ void __launch_bounds__(128) attn_tc_kernel(
    const bf16* __restrict__ q, const bf16* __restrict__ k,
    const bf16* __restrict__ v, bf16* __restrict__ ctx)
{
    __shared__ __align__(16) bf16 Qs[64*ATS];
    __shared__ __align__(16) bf16 Ks[2][64*ATS];
    __shared__ __align__(16) bf16 Vs[2][64*ATS];

    int qt = gridDim.x - 1 - blockIdx.x;
    int h = blockIdx.y, b = blockIdx.z;
    int q0 = qt * 64;
    int tid = threadIdx.x, lane = tid & 31, w = tid >> 5;

    int srow = tid >> 1;
    int sc0  = (tid & 1) * 4;
    const bf16* qg = q + (size_t)(b*SS + q0 + srow)*DDIM + h*DH + sc0*8;
    unsigned qDst = smem_u32(&Qs[srow*ATS]) + sc0*16;
    unsigned kDst = smem_u32(&Ks[0][srow*ATS]) + sc0*16;
    unsigned vDst = smem_u32(&Vs[0][srow*ATS]) + sc0*16;
    const bf16* kg0 = k + (size_t)(b*SS + srow)*DDIM + h*DH + sc0*8;
    const bf16* vg0 = v + (size_t)(b*SS + srow)*DDIM + h*DH + sc0*8;

    auto issueKV = [&](int kt, int buf) {
        unsigned kd = kDst + buf*(64*ATS*2);
        unsigned vd = vDst + buf*(64*ATS*2);
        const bf16* kgp = kg0 + (size_t)kt*DDIM;
        const bf16* vgp = vg0 + (size_t)kt*DDIM;
        #pragma unroll
        for (int j = 0; j < 4; j++) {
            cp_async16(kd + j*16, kgp + j*8, 16);
            cp_async16(vd + j*16, vgp + j*8, 16);
        }
        cp_commit();
    };

    #pragma unroll
    for (int j = 0; j < 4; j++) cp_async16(qDst + j*16, qg + j*8, 16);
    issueKV(0, 0);

    int l15 = lane & 15;
    int lH8 = (lane >> 4) << 3;
    int lB8 = ((lane >> 3) & 1) << 3;
    int bRowP = lH8 + (lane & 7);

    unsigned qf[4][4];
    float m0 = -1e30f, m1 = -1e30f, l0 = 0.f, l1 = 0.f;
    float oa[8][4];
    #pragma unroll
    for (int j = 0; j < 8; j++)
        #pragma unroll
        for (int e = 0; e < 4; e++) oa[j][e] = 0.f;

    int r0loc = lane >> 2;
    int rowg0 = q0 + 16*w + r0loc;
    int rowg1 = rowg0 + 8;
    int c2 = (lane & 3) * 2;

    int nt = q0/64 + 1;
    for (int t = 0; t < nt; t++) {
        cp_wait<0>();
        __syncthreads();
        if (t == 0) {
            #pragma unroll
            for (int kk = 0; kk < 4; kk++)
                ldsm_x4(qf[kk], smem_u32(&Qs[(16*w + l15)*ATS + kk*16 + lH8]));
        }
        if (t + 1 < nt) issueKV((t+1)*64, (t+1) & 1);

        int buf = t & 1;
        int kt = t * 64;
        const bf16* KsB = Ks[buf];
        const bf16* VsB = Vs[buf];

        float sf[8][4];
        #pragma unroll
        for (int j = 0; j < 8; j++)
            #pragma unroll
            for (int e = 0; e < 4; e++) sf[j][e] = 0.f;
        #pragma unroll
        for (int kk = 0; kk < 4; kk++) {
            #pragma unroll
            for (int j2 = 0; j2 < 4; j2++) {
                unsigned bk[4];
                ldsm_x4(bk, smem_u32(&KsB[(16*j2 + bRowP)*ATS + kk*16 + lB8]));
                mma_bf16(sf[2*j2+0], qf[kk], bk[0], bk[1]);
                mma_bf16(sf[2*j2+1], qf[kk], bk[2], bk[3]);
            }
        }
        #pragma unroll
        for (int j = 0; j < 8; j++)
            #pragma unroll
            for (int e = 0; e < 4; e++) sf[j][e] *= 0.125f;
        if (kt == q0) {
            #pragma unroll
            for (int j = 0; j < 8; j++) {
                int col = kt + 8*j + c2;
                if (col     > rowg0) sf[j][0] = -1e30f;
                if (col + 1 > rowg0) sf[j][1] = -1e30f;
                if (col     > rowg1) sf[j][2] = -1e30f;
                if (col + 1 > rowg1) sf[j][3] = -1e30f;
            }
        }
        float tm0 = -1e30f, tm1 = -1e30f;
        #pragma unroll
        for (int j = 0; j < 8; j++) {
            tm0 = fmaxf(tm0, fmaxf(sf[j][0], sf[j][1]));
            tm1 = fmaxf(tm1, fmaxf(sf[j][2], sf[j][3]));
        }
        tm0 = fmaxf(tm0, __shfl_xor_sync(0xffffffffu, tm0, 1));
        tm0 = fmaxf(tm0, __shfl_xor_sync(0xffffffffu, tm0, 2));
        tm1 = fmaxf(tm1, __shfl_xor_sync(0xffffffffu, tm1, 1));
        tm1 = fmaxf(tm1, __shfl_xor_sync(0xffffffffu, tm1, 2));
        float nm0 = fmaxf(m0, tm0), nm1 = fmaxf(m1, tm1);
        float cc0 = __expf(m0 - nm0), cc1 = __expf(m1 - nm1);
        l0 *= cc0; l1 *= cc1;
        #pragma unroll
        for (int j = 0; j < 8; j++) {
            oa[j][0] *= cc0; oa[j][1] *= cc0;
            oa[j][2] *= cc1; oa[j][3] *= cc1;
        }
        float ps0 = 0.f, ps1 = 0.f;
        #pragma unroll
        for (int j = 0; j < 8; j++) {
            sf[j][0] = __expf(sf[j][0] - nm0);
            sf[j][1] = __expf(sf[j][1] - nm0);
            sf[j][2] = __expf(sf[j][2] - nm1);
            sf[j][3] = __expf(sf[j][3] - nm1);
            ps0 += sf[j][0] + sf[j][1];
            ps1 += sf[j][2] + sf[j][3];
        }
        l0 += ps0; l1 += ps1; m0 = nm0; m1 = nm1;

        unsigned pf[4][4];
        #pragma unroll
        for (int t2 = 0; t2 < 4; t2++) {
            pf[t2][0] = pack_bf16(sf[2*t2][0],   sf[2*t2][1]);
            pf[t2][1] = pack_bf16(sf[2*t2][2],   sf[2*t2][3]);
            pf[t2][2] = pack_bf16(sf[2*t2+1][0], sf[2*t2+1][1]);
            pf[t2][3] = pack_bf16(sf[2*t2+1][2], sf[2*t2+1][3]);
        }
        #pragma unroll
        for (int t2 = 0; t2 < 4; t2++) {
            #pragma unroll
            for (int g = 0; g < 4; g++) {
                unsigned bv[4];
                ldsm_x4_t(bv, smem_u32(&VsB[(16*t2 + l15)*ATS + 16*g + lH8]));
                mma_bf16(oa[2*g+0], pf[t2], bv[0], bv[1]);
                mma_bf16(oa[2*g+1], pf[t2], bv[2], bv[3]);
            }
        }
        __syncthreads();
    }

    l0 += __shfl_xor_sync(0xffffffffu, l0, 1);
    l0 += __shfl_xor_sync(0xffffffffu, l0, 2);
    l1 += __shfl_xor_sync(0xffffffffu, l1, 1);
    l1 += __shfl_xor_sync(0xffffffffu, l1, 2);
    float inv0 = 1.f / l0, inv1 = 1.f / l1;

    bf16* c0p = ctx + (size_t)(b*SS + rowg0)*DDIM + h*DH + c2;
    bf16* c1p = ctx + (size_t)(b*SS + rowg1)*DDIM + h*DH + c2;
    #pragma unroll
    for (int j = 0; j < 8; j++) {
        *(bf162*)(c0p + 8*j) = __floats2bfloat162_rn(oa[j][0]*inv0, oa[j][1]*inv0);
        *(bf162*)(c1p + 8*j) = __floats2bfloat162_rn(oa[j][2]*inv1, oa[j][3]*inv1);
    }
}

// ---------------- gate ----------------
__global__ void zero_cnt_kernel(int* cnt) {
    if (threadIdx.x < EE) cnt[threadIdx.x] = 0;
}

__global__ void gate_kernel(const float* __restrict__ h, const float* __restrict__ gw,
                            const float* __restrict__ gb, float* __restrict__ sc,
                            int* __restrict__ cnt, int* __restrict__ list)
{
    int warp = (blockIdx.x * blockDim.x + threadIdx.x) >> 5;
    if (warp >= NTOK) return;
    int lane = threadIdx.x & 31;
    float a[8] = {0,0,0,0,0,0,0,0};
    const float* hr = h + (size_t)warp * DDIM;
    for (int d = lane; d < DDIM; d += 32) {
        float hv = hr[d];
        float4 w0 = *(const float4*)(gw + (size_t)d*EE);
        float4 w1 = *(const float4*)(gw + (size_t)d*EE + 4);
        a[0]+=hv*w0.x; a[1]+=hv*w0.y; a[2]+=hv*w0.z; a[3]+=hv*w0.w;
        a[4]+=hv*w1.x; a[5]+=hv*w1.y; a[6]+=hv*w1.z; a[7]+=hv*w1.w;
    }
    #pragma unroll
    for (int e = 0; e < 8; e++)
        #pragma unroll
        for (int o = 16; o > 0; o >>= 1)
            a[e] += __shfl_down_sync(0xffffffffu, a[e], o);
    if (lane == 0) {
        float lg[8];
        #pragma unroll
        for (int e = 0; e < 8; e++) lg[e] = a[e] + gb[e];
        int i0 = 0; float v0 = lg[0];
        #pragma unroll
        for (int e = 1; e < 8; e++) if (lg[e] > v0) { v0 = lg[e]; i0 = e; }
        int i1 = -1; float v1 = -3.0e38f;
        #pragma unroll
        for (int e = 0; e < 8; e++) if (e != i0 && lg[e] > v1) { v1 = lg[e]; i1 = e; }
        float e1 = __expf(v1 - v0);
        float s0 = 1.f / (1.f + e1);
        float s1 = e1 * s0;
        sc[2*warp]   = s0;
        sc[2*warp+1] = s1;
        int p0 = atomicAdd(&cnt[i0], 1);
        list[(size_t)i0*CAP + p0] = 2*warp;
        int p1 = atomicAdd(&cnt[i1], 1);
        list[(size_t)i1*CAP + p1] = 2*warp + 1;
    }
}

// ---------------- combine: warp-per-row (no barriers, no smem) ----------------
__global__ void combine_kernel(const float* __restrict__ h, const float* __restrict__ o2,
                               const float* __restrict__ sc, const float* __restrict__ xa,
                               const float* __restrict__ g, const float* __restrict__ b,
                               float* __restrict__ out)
{
    int wid = threadIdx.x >> 5, lane = threadIdx.x & 31;
    int t = blockIdx.x * 8 + wid;
    const float* hr = h + (size_t)t*DDIM;
    const float* r0 = o2 + (size_t)(2*t)*DDIM;
    const float* r1 = o2 + (size_t)(2*t+1)*DDIM;
    float s0 = sc[2*t], s1 = sc[2*t+1];

    float4 tv[6];
    float s = 0.f;
    #pragma unroll
    for (int j = 0; j < 6; j++) {
        int d = lane*4 + j*128;
        float4 hv = *(const float4*)(hr + d);
        float4 a0 = *(const float4*)(r0 + d);
        float4 a1 = *(const float4*)(r1 + d);
        tv[j].x = hv.x + s0*a0.x + s1*a1.x;
        tv[j].y = hv.y + s0*a0.y + s1*a1.y;
        tv[j].z = hv.z + s0*a0.z + s1*a1.z;
        tv[j].w = hv.w + s0*a0.w + s1*a1.w;
        s += (tv[j].x + tv[j].y) + (tv[j].z + tv[j].w);
    }
    #pragma unroll
    for (int o = 16; o > 0; o >>= 1) s += __shfl_xor_sync(0xffffffffu, s, o);
    float mean = s * (1.f / DDIM);

    float vs = 0.f;
    #pragma unroll
    for (int j = 0; j < 6; j++) {
        float a0 = tv[j].x - mean, a1 = tv[j].y - mean;
        float a2 = tv[j].z - mean, a3 = tv[j].w - mean;
        vs += (a0*a0 + a1*a1) + (a2*a2 + a3*a3);
    }
    #pragma unroll
    for (int o = 16; o > 0; o >>= 1) vs += __shfl_xor_sync(0xffffffffu, vs, o);
    float rstd = rsqrtf(vs * (1.f / DDIM) + 1e-5f);

    #pragma unroll
    for (int j = 0; j < 6; j++) {
        int d = lane*4 + j*128;
        float4 gg = *(const float4*)(g + d);
        float4 bb = *(const float4*)(b + d);
        float4 xv = *(const float4*)(xa + (size_t)t*DDIM + d);
        float4 o;
        o.x = xv.x + (tv[j].x - mean)*rstd*gg.x + bb.x;
        o.y = xv.y + (tv[j].y - mean)*rstd*gg.y + bb.y;
        o.z = xv.z + (tv[j].z - mean)*rstd*gg.z + bb.z;
        o.w = xv.w + (tv[j].w - mean)*rstd*gg.w + bb.w;
        *(float4*)(out + (size_t)t*DDIM + d) = o;
    }
}

// ---------------- launch ----------------
extern "C" void kernel_launch(void* const* d_in, const int* in_sizes, int n_in,
                              void* d_out, int out_size)
{
    const float* x        = (const float*)d_in[0];
    const float* ln_a_g   = (const float*)d_in[2];
    const float* ln_a_b   = (const float*)d_in[3];
    const float* wq       = (const float*)d_in[4];
    const float* bq       = (const float*)d_in[5];
    const float* wk       = (const float*)d_in[6];
    const float* bk       = (const float*)d_in[7];
    const float* wv       = (const float*)d_in[8];
    const float* bv       = (const float*)d_in[9];
    const float* wo       = (const float*)d_in[10];
    const float* bo       = (const float*)d_in[11];
    const float* ln_f_g   = (const float*)d_in[12];
    const float* ln_f_b   = (const float*)d_in[13];
    const float* gate_w   = (const float*)d_in[14];
    const float* gate_b   = (const float*)d_in[15];
    const float* w1       = (const float*)d_in[16];
    const float* b1       = (const float*)d_in[17];
    const float* w2       = (const float*)d_in[18];
    const float* b2       = (const float*)d_in[19];
    const float* moe_g    = (const float*)d_in[20];
    const float* moe_b    = (const float*)d_in[21];
    float* out = (float*)d_out;

    bf16 *a, *qb, *kb, *vb, *ctx, *hrb, *y1, *bwq, *bwk, *bwv, *bwo, *bw1, *bw2;
    float *xa, *h, *o2, *sc;
    int *cnt, *list;
    cudaGetSymbolAddress((void**)&a,   g_a);
    cudaGetSymbolAddress((void**)&qb,  g_q);
    cudaGetSymbolAddress((void**)&kb,  g_k);
    cudaGetSymbolAddress((void**)&vb,  g_v);
    cudaGetSymbolAddress((void**)&ctx, g_ctx);
    cudaGetSymbolAddress((void**)&xa,  g_xa);
    cudaGetSymbolAddress((void**)&h,   g_h);
    cudaGetSymbolAddress((void**)&hrb, g_hr);
    cudaGetSymbolAddress((void**)&y1,  g_y1);
    cudaGetSymbolAddress((void**)&o2,  g_o2);
    cudaGetSymbolAddress((void**)&sc,  g_sc);
    cudaGetSymbolAddress((void**)&cnt, g_cnt);
    cudaGetSymbolAddress((void**)&list,g_list);
    cudaGetSymbolAddress((void**)&bwq, g_bwq);
    cudaGetSymbolAddress((void**)&bwk, g_bwk);
    cudaGetSymbolAddress((void**)&bwv, g_bwv);
    cudaGetSymbolAddress((void**)&bwo, g_bwo);
    cudaGetSymbolAddress((void**)&bw1, g_bw1);
    cudaGetSymbolAddress((void**)&bw2, g_bw2);

    cudaFuncSetAttribute(bgemm_k<false,false,false,false,true,true>,
                         cudaFuncAttributeMaxDynamicSharedMemorySize, GSMEM);
    cudaFuncSetAttribute(bgemm_k<false,false,false,true,false,false>,
                         cudaFuncAttributeMaxDynamicSharedMemorySize, GSMEM);
    cudaFuncSetAttribute(bgemm_k<true,false,true,false,true,false>,
                         cudaFuncAttributeMaxDynamicSharedMemorySize, GSMEM);
    cudaFuncSetAttribute(bgemm_k<true,true,false,false,false,false>,
                         cudaFuncAttributeMaxDynamicSharedMemorySize, GSMEM);

    // 0) weight conversions f32 -> bf16
    {
        int nqkv4 = DDIM*DDIM/4;
        conv4_bf16_kernel<<<dim3((nqkv4 + 255)/256, 1, 4), 256>>>(
            wq, wk, wv, wo, bwq, bwk, bwv, bwo, nqkv4);
        int nff4 = EE*DDIM*HID/4;
        int gf = (nff4 + 1023)/1024;
        conv_bf16_ilp_kernel<<<gf, 256>>>(w1, bw1, nff4);
        conv_bf16_ilp_kernel<<<gf, 256>>>(w2, bw2, nff4);
    }

    // 1) a = bf16(ln_attn(x))  (warp-per-row)
    ln_kernel<1><<<NTOK/8, 256>>>(x, ln_a_g, ln_a_b, nullptr, a);

    // 2) fused q,k,v projections -> bf16 outputs
    dim3 gQKV(DDIM/128, NTOK/128, 3);
    bgemm_k<false,false,false,false,true,true><<<gQKV, 256, GSMEM>>>(
        NTOK, DDIM, DDIM, a, DDIM, bwq, bq, nullptr, (float*)qb, DDIM, nullptr, nullptr,
        bwk, bk, (float*)kb, bwv, bv, (float*)vb);

    // 3) tensor-core flash attention (causal), ctx bf16
    attn_tc_kernel<<<dim3(SS/64, HH, BB), 128>>>(qb, kb, vb, ctx);

    // 4) xa = x + ctx @ wo + bo
    dim3 gO(DDIM/128, NTOK/128, 1);
    bgemm_k<false,false,false,true,false,false><<<gO, 256, GSMEM>>>(
        NTOK, DDIM, DDIM, ctx, DDIM, bwo, bo, x, xa, DDIM, nullptr, nullptr,
        nullptr, nullptr, nullptr, nullptr, nullptr, nullptr);

    // 5) h = ln_ff(xa) (f32) + hr (bf16)  (warp-per-row)
    ln_kernel<2><<<NTOK/8, 256>>>(xa, ln_f_g, ln_f_b, h, hrb);

    // 6) gate: top-2 per token + per-expert pair lists
    zero_cnt_kernel<<<1, 32>>>(cnt);
    gate_kernel<<<NTOK/8, 256>>>(h, gate_w, gate_b, sc, cnt, list);

    // 7) expert GEMM1: y1[pair] = bf16(relu(hr[token] @ w1[e] + b1[e]))
    bgemm_k<true,false,true,false,true,false><<<dim3(HID/128, CAP/128, EE), 256, GSMEM>>>(
        CAP, HID, DDIM, hrb, DDIM, bw1, b1, nullptr, (float*)y1, HID, list, cnt,
        nullptr, nullptr, nullptr, nullptr, nullptr, nullptr);

    // 8) expert GEMM2: o2[pair] = y1[pair] @ w2[e] + b2[e]
    bgemm_k<true,true,false,false,false,false><<<dim3(DDIM/128, CAP/128, EE), 256, GSMEM>>>(
        CAP, DDIM, HID, y1, HID, bw2, b2, nullptr, o2, DDIM, list, cnt,
        nullptr, nullptr, nullptr, nullptr, nullptr, nullptr);

    // 9) combine + post-LN + final residual (warp-per-row)
    combine_kernel<<<NTOK/8, 256>>>(h, o2, sc, xa, moe_g, moe_b, out);
}

// round 16
// speedup vs baseline: 1.3597x; 1.0286x over previous
#include <cuda_runtime.h>
#include <cuda_bf16.h>

#define BB 4
#define SS 1024
#define DDIM 768
#define HH 12
#define EE 8
#define HID 3072
#define DH 64
#define NTOK (BB*SS)
#define CAP (NTOK*2)

typedef __nv_bfloat16 bf16;
typedef __nv_bfloat162 bf162;

// ---------------- scratch ----------------
__device__ bf16  g_a[NTOK*DDIM];
__device__ bf16  g_q[NTOK*DDIM];
__device__ bf16  g_k[NTOK*DDIM];
__device__ bf16  g_v[NTOK*DDIM];
__device__ bf16  g_ctx[NTOK*DDIM];
__device__ float g_xa[NTOK*DDIM];
__device__ float g_h[NTOK*DDIM];
__device__ bf16  g_hr[NTOK*DDIM];
__device__ bf16  g_y1[CAP*HID];
__device__ float g_o2[CAP*DDIM];
__device__ float g_sc[CAP];
__device__ int   g_cnt[EE];
__device__ int   g_list[EE*CAP];
__device__ bf16  g_bwq[DDIM*DDIM];
__device__ bf16  g_bwk[DDIM*DDIM];
__device__ bf16  g_bwv[DDIM*DDIM];
__device__ bf16  g_bwo[DDIM*DDIM];
__device__ bf16  g_bw1[EE*DDIM*HID];
__device__ bf16  g_bw2[EE*HID*DDIM];

// ---------------- helpers ----------------
__device__ __forceinline__ unsigned smem_u32(const void* p) {
    return (unsigned)__cvta_generic_to_shared(p);
}
__device__ __forceinline__ void cp_async16(unsigned dst, const void* src, int srcsize) {
    asm volatile("cp.async.cg.shared.global [%0], [%1], 16, %2;"
                 :: "r"(dst), "l"(src), "r"(srcsize));
}
__device__ __forceinline__ void cp_commit() { asm volatile("cp.async.commit_group;"); }
template<int N>
__device__ __forceinline__ void cp_wait() { asm volatile("cp.async.wait_group %0;" :: "n"(N)); }

__device__ __forceinline__ void ldsm_x4(unsigned* r, unsigned addr) {
    asm volatile("ldmatrix.sync.aligned.m8n8.x4.shared.b16 {%0,%1,%2,%3}, [%4];"
        : "=r"(r[0]), "=r"(r[1]), "=r"(r[2]), "=r"(r[3]) : "r"(addr));
}
__device__ __forceinline__ void ldsm_x4_t(unsigned* r, unsigned addr) {
    asm volatile("ldmatrix.sync.aligned.m8n8.x4.trans.shared.b16 {%0,%1,%2,%3}, [%4];"
        : "=r"(r[0]), "=r"(r[1]), "=r"(r[2]), "=r"(r[3]) : "r"(addr));
}
__device__ __forceinline__ void mma_bf16(float c[4], const unsigned a[4],
                                         unsigned b0, unsigned b1) {
    asm volatile("mma.sync.aligned.m16n8k16.row.col.f32.bf16.bf16.f32 "
        "{%0,%1,%2,%3}, {%4,%5,%6,%7}, {%8,%9}, {%0,%1,%2,%3};"
        : "+f"(c[0]), "+f"(c[1]), "+f"(c[2]), "+f"(c[3])
        : "r"(a[0]), "r"(a[1]), "r"(a[2]), "r"(a[3]), "r"(b0), "r"(b1));
}
__device__ __forceinline__ unsigned pack_bf16(float a, float b) {
    bf162 t = __floats2bfloat162_rn(a, b);
    return *(unsigned*)&t;
}

// ---------------- weight conversion f32 -> bf16 ----------------
__global__ void conv4_bf16_kernel(const float* __restrict__ s0, const float* __restrict__ s1,
                                  const float* __restrict__ s2, const float* __restrict__ s3,
                                  bf16* d0, bf16* d1, bf16* d2, bf16* d3, int n4) {
    const float* s; bf16* d;
    switch (blockIdx.z) {
        case 0: s = s0; d = d0; break;
        case 1: s = s1; d = d1; break;
        case 2: s = s2; d = d2; break;
        default: s = s3; d = d3; break;
    }
    int i = blockIdx.x * blockDim.x + threadIdx.x;
    if (i < n4) {
        float4 v = *(const float4*)(s + (size_t)i*4);
        bf162* dd = (bf162*)(d + (size_t)i*4);
        dd[0] = __floats2bfloat162_rn(v.x, v.y);
        dd[1] = __floats2bfloat162_rn(v.z, v.w);
    }
}

__global__ void conv_bf16_ilp_kernel(const float* __restrict__ src, bf16* __restrict__ dst, int n4) {
    int base = blockIdx.x * (blockDim.x * 4) + threadIdx.x;
    float4 v[4];
    int idx[4];
    #pragma unroll
    for (int j = 0; j < 4; j++) {
        idx[j] = base + j * blockDim.x;
        if (idx[j] < n4) v[j] = *(const float4*)(src + (size_t)idx[j]*4);
    }
    #pragma unroll
    for (int j = 0; j < 4; j++) {
        if (idx[j] < n4) {
            bf162* d = (bf162*)(dst + (size_t)idx[j]*4);
            d[0] = __floats2bfloat162_rn(v[j].x, v[j].y);
            d[1] = __floats2bfloat162_rn(v[j].z, v[j].w);
        }
    }
}

// ---------------- layernorm: warp-per-row ----------------
template<int MODE>
__global__ void ln_kernel(const float* __restrict__ x, const float* __restrict__ g,
                          const float* __restrict__ b, float* __restrict__ out,
                          bf16* __restrict__ out_b) {
    int wid = threadIdx.x >> 5, lane = threadIdx.x & 31;
    int row = blockIdx.x * 8 + wid;
    const float* xr = x + (size_t)row * DDIM;

    float4 v[6];
    float s = 0.f;
    #pragma unroll
    for (int j = 0; j < 6; j++) {
        v[j] = *(const float4*)(xr + lane*4 + j*128);
        s += (v[j].x + v[j].y) + (v[j].z + v[j].w);
    }
    #pragma unroll
    for (int o = 16; o > 0; o >>= 1) s += __shfl_xor_sync(0xffffffffu, s, o);
    float mean = s * (1.f / DDIM);

    float vs = 0.f;
    #pragma unroll
    for (int j = 0; j < 6; j++) {
        float a0 = v[j].x - mean, a1 = v[j].y - mean;
        float a2 = v[j].z - mean, a3 = v[j].w - mean;
        vs += (a0*a0 + a1*a1) + (a2*a2 + a3*a3);
    }
    #pragma unroll
    for (int o = 16; o > 0; o >>= 1) vs += __shfl_xor_sync(0xffffffffu, vs, o);
    float rstd = rsqrtf(vs * (1.f / DDIM) + 1e-5f);

    #pragma unroll
    for (int j = 0; j < 6; j++) {
        int d = lane*4 + j*128;
        float4 gg = *(const float4*)(g + d);
        float4 bb = *(const float4*)(b + d);
        float y0 = (v[j].x - mean)*rstd*gg.x + bb.x;
        float y1 = (v[j].y - mean)*rstd*gg.y + bb.y;
        float y2 = (v[j].z - mean)*rstd*gg.z + bb.z;
        float y3 = (v[j].w - mean)*rstd*gg.w + bb.w;
        bf162 p0 = __floats2bfloat162_rn(y0, y1);
        bf162 p1 = __floats2bfloat162_rn(y2, y3);
        uint2 pk = make_uint2(*(unsigned*)&p0, *(unsigned*)&p1);
        *(uint2*)(out_b + (size_t)row*DDIM + d) = pk;
        if (MODE == 2)
            *(float4*)(out + (size_t)row*DDIM + d) = make_float4(y0, y1, y2, y3);
    }
}

// ---------------- bf16 tensor-core GEMM: 128x128 CTA, 8 warps 32x64 ----------------
#define ASTG 5120
#define BSTG 4352
#define ABYTES 10240
#define BBYTES 8704
#define GSMEM (4*(ABYTES + BBYTES) + 512)

template<bool GATHER, bool AROW_PAIR, bool RELU, bool RESID, bool OUTBF16, bool QKV3>
__global__ __launch_bounds__(256, 2) void bgemm_k(
    int M, int N, int K,
    const bf16* __restrict__ A, int lda,
    const bf16* __restrict__ Bm,
    const float* __restrict__ bias,
    const float* __restrict__ resid,
    float* __restrict__ C, int ldc,
    const int* __restrict__ rowlist,
    const int* __restrict__ cnt,
    const bf16* Bm2, const float* bias2, float* C2,
    const bf16* Bm3, const float* bias3, float* C3)
{
    extern __shared__ __align__(16) char smem_raw[];
    bf16* AsBase = (bf16*)smem_raw;
    bf16* BsBase = (bf16*)smem_raw + 4*ASTG;
    int*  rowsS  = (int*)(smem_raw + 4*(ABYTES + BBYTES));

    if (QKV3) {
        int z = blockIdx.z;
        if (z == 1) { Bm = Bm2; bias = bias2; C = C2; }
        else if (z == 2) { Bm = Bm3; bias = bias3; C = C3; }
    }
    if (GATHER) {
        int e = blockIdx.z;
        Bm      += (size_t)e * K * N;
        bias    += (size_t)e * N;
        rowlist += (size_t)e * CAP;
        cnt     += e;
    }
    int m0 = blockIdx.y * 128, n0 = blockIdx.x * 128;
    int tid = threadIdx.x, lane = tid & 31, wid = tid >> 5;
    int warpM = wid & 3, warpN = wid >> 2;

    if (GATHER) {
        int Meff = *cnt;
        if (m0 >= Meff) return;
        if (tid < 128) {
            int gidx = m0 + tid;
            rowsS[tid] = (gidx < Meff) ? rowlist[gidx] : -1;
        }
        __syncthreads();
    }

    int lm  = tid >> 1;
    int acb = (tid & 1) << 1;
    const bf16* Aptr;
    int asz = 16;
    if (GATHER) {
        int pr = rowsS[lm];
        if (pr < 0) { Aptr = A; asz = 0; }
        else Aptr = A + (size_t)(AROW_PAIR ? pr : (pr >> 1)) * lda + acb*8;
    } else {
        Aptr = A + (size_t)(m0 + lm) * lda + acb*8;
    }
    unsigned aD0 = smem_u32(&AsBase[lm*40]) + acb*16;

    int lbr = tid >> 3;
    int bcb = (tid & 7) << 1;
    const bf16* Bptr = Bm + (size_t)lbr * N + n0 + bcb*8;
    unsigned bD0 = smem_u32(&BsBase[lbr*136]) + bcb*16;

    int lane8 = lane & 7, laneH = lane & 8, laneK = (lane & 16) >> 1;
    unsigned aAddr[2], bAddr[4];
    #pragma unroll
    for (int mt = 0; mt < 2; mt++) {
        int r = warpM*32 + mt*16 + lane8 + laneH;
        aAddr[mt] = smem_u32(&AsBase[r*40 + laneK]);
    }
    #pragma unroll
    for (int ntp = 0; ntp < 4; ntp++) {
        int kr = lane8 + laneH;
        int nc = warpN*64 + ntp*16 + laneK;
        bAddr[ntp] = smem_u32(&BsBase[kr*136 + nc]);
    }

    float acc[2][8][4];
    #pragma unroll
    for (int i = 0; i < 2; i++)
        #pragma unroll
        for (int j = 0; j < 8; j++)
            #pragma unroll
            for (int q = 0; q < 4; q++) acc[i][j][q] = 0.f;

    auto issueStage = [&](int k0, int buf) {
        unsigned ad = aD0 + buf*ABYTES;
        cp_async16(ad,      Aptr + k0,     asz);
        cp_async16(ad + 16, Aptr + k0 + 8, asz);
        const bf16* bs = Bptr + (size_t)k0 * N;
        unsigned bd = bD0 + buf*BBYTES;
        cp_async16(bd,      bs,     16);
        cp_async16(bd + 16, bs + 8, 16);
        cp_commit();
    };

    int nStages = K >> 5;
    issueStage(0, 0);
    issueStage(32, 1);
    issueStage(64, 2);

    for (int s = 0; s < nStages; s++) {
        int rem = nStages - 1 - s;
        if (rem >= 2) cp_wait<2>();
        else if (rem == 1) cp_wait<1>();
        else cp_wait<0>();
        __syncthreads();
        if (s + 3 < nStages) issueStage((s + 3) << 5, (s + 3) & 3);

        int buf = s & 3;
        unsigned aOff = buf*ABYTES, bOff = buf*BBYTES;
        #pragma unroll
        for (int kk = 0; kk < 32; kk += 16) {
            unsigned af[2][4];
            ldsm_x4(af[0], aAddr[0] + aOff + kk*2);
            ldsm_x4(af[1], aAddr[1] + aOff + kk*2);
            #pragma unroll
            for (int ntp = 0; ntp < 4; ntp++) {
                unsigned bfr[4];
                ldsm_x4_t(bfr, bAddr[ntp] + bOff + kk*272);
                #pragma unroll
                for (int mt = 0; mt < 2; mt++) {
                    mma_bf16(acc[mt][ntp*2+0], af[mt], bfr[0], bfr[1]);
                    mma_bf16(acc[mt][ntp*2+1], af[mt], bfr[2], bfr[3]);
                }
            }
        }
    }

    #pragma unroll
    for (int mt = 0; mt < 2; mt++) {
        int rr0 = warpM*32 + mt*16 + (lane >> 2);
        #pragma unroll
        for (int half = 0; half < 2; half++) {
            int rloc = rr0 + half*8;
            int crow;
            if (GATHER) {
                int pr = rowsS[rloc];
                if (pr < 0) continue;
                crow = pr;
            } else {
                crow = m0 + rloc;
            }
            #pragma unroll
            for (int nt = 0; nt < 8; nt++) {
                int col = n0 + warpN*64 + nt*8 + (lane & 3)*2;
                float v0 = acc[mt][nt][half*2 + 0] + bias[col];
                float v1 = acc[mt][nt][half*2 + 1] + bias[col + 1];
                if (RELU) { v0 = fmaxf(v0, 0.f); v1 = fmaxf(v1, 0.f); }
                if (RESID) {
                    const float* rp = resid + (size_t)crow*ldc + col;
                    v0 += rp[0]; v1 += rp[1];
                }
                if (OUTBF16) {
                    *(bf162*)((bf16*)C + (size_t)crow*ldc + col) =
                        __floats2bfloat162_rn(v0, v1);
                } else {
                    *(float2*)(C + (size_t)crow*ldc + col) = make_float2(v0, v1);
                }
            }
        }
    }
}

// ---------------- tensor-core flash attention (causal, bf16 mma) ----------------
#define ATS 72

__global__ void __launch_bounds__(128) attn_tc_kernel(
    const bf16* __restrict__ q, const bf16* __restrict__ k,
    const bf16* __restrict__ v, bf16* __restrict__ ctx)
{
    __shared__ __align__(16) bf16 Qs[64*ATS];
    __shared__ __align__(16) bf16 Ks[2][64*ATS];
    __shared__ __align__(16) bf16 Vs[2][64*ATS];

    int qt = gridDim.x - 1 - blockIdx.x;
    int h = blockIdx.y, b = blockIdx.z;
    int q0 = qt * 64;
    int tid = threadIdx.x, lane = tid & 31, w = tid >> 5;

    int srow = tid >> 1;
    int sc0  = (tid & 1) * 4;
    const bf16* qg = q + (size_t)(b*SS + q0 + srow)*DDIM + h*DH + sc0*8;
    unsigned qDst = smem_u32(&Qs[srow*ATS]) + sc0*16;
    unsigned kDst = smem_u32(&Ks[0][srow*ATS]) + sc0*16;
    unsigned vDst = smem_u32(&Vs[0][srow*ATS]) + sc0*16;
    const bf16* kg0 = k + (size_t)(b*SS + srow)*DDIM + h*DH + sc0*8;
    const bf16* vg0 = v + (size_t)(b*SS + srow)*DDIM + h*DH + sc0*8;

    auto issueKV = [&](int kt, int buf) {
        unsigned kd = kDst + buf*(64*ATS*2);
        unsigned vd = vDst + buf*(64*ATS*2);
        const bf16* kgp = kg0 + (size_t)kt*DDIM;
        const bf16* vgp = vg0 + (size_t)kt*DDIM;
        #pragma unroll
        for (int j = 0; j < 4; j++) {
            cp_async16(kd + j*16, kgp + j*8, 16);
            cp_async16(vd + j*16, vgp + j*8, 16);
        }
        cp_commit();
    };

    #pragma unroll
    for (int j = 0; j < 4; j++) cp_async16(qDst + j*16, qg + j*8, 16);
    issueKV(0, 0);

    int l15 = lane & 15;
    int lH8 = (lane >> 4) << 3;
    int lB8 = ((lane >> 3) & 1) << 3;
    int bRowP = lH8 + (lane & 7);

    unsigned qf[4][4];
    float m0 = -1e30f, m1 = -1e30f, l0 = 0.f, l1 = 0.f;
    float oa[8][4];
    #pragma unroll
    for (int j = 0; j < 8; j++)
        #pragma unroll
        for (int e = 0; e < 4; e++) oa[j][e] = 0.f;

    int r0loc = lane >> 2;
    int rowg0 = q0 + 16*w + r0loc;
    int rowg1 = rowg0 + 8;
    int c2 = (lane & 3) * 2;

    int nt = q0/64 + 1;
    for (int t = 0; t < nt; t++) {
        cp_wait<0>();
        __syncthreads();
        if (t == 0) {
            #pragma unroll
            for (int kk = 0; kk < 4; kk++)
                ldsm_x4(qf[kk], smem_u32(&Qs[(16*w + l15)*ATS + kk*16 + lH8]));
        }
        if (t + 1 < nt) issueKV((t+1)*64, (t+1) & 1);

        int buf = t & 1;
        int kt = t * 64;
        const bf16* KsB = Ks[buf];
        const bf16* VsB = Vs[buf];

        float sf[8][4];
        #pragma unroll
        for (int j = 0; j < 8; j++)
            #pragma unroll
            for (int e = 0; e < 4; e++) sf[j][e] = 0.f;
        #pragma unroll
        for (int kk = 0; kk < 4; kk++) {
            #pragma unroll
            for (int j2 = 0; j2 < 4; j2++) {
                unsigned bk[4];
                ldsm_x4(bk, smem_u32(&KsB[(16*j2 + bRowP)*ATS + kk*16 + lB8]));
                mma_bf16(sf[2*j2+0], qf[kk], bk[0], bk[1]);
                mma_bf16(sf[2*j2+1], qf[kk], bk[2], bk[3]);
            }
        }
        #pragma unroll
        for (int j = 0; j < 8; j++)
            #pragma unroll
            for (int e = 0; e < 4; e++) sf[j][e] *= 0.125f;
        if (kt == q0) {
            #pragma unroll
            for (int j = 0; j < 8; j++) {
                int col = kt + 8*j + c2;
                if (col     > rowg0) sf[j][0] = -1e30f;
                if (col + 1 > rowg0) sf[j][1] = -1e30f;
                if (col     > rowg1) sf[j][2] = -1e30f;
                if (col + 1 > rowg1) sf[j][3] = -1e30f;
            }
        }
        float tm0 = -1e30f, tm1 = -1e30f;
        #pragma unroll
        for (int j = 0; j < 8; j++) {
            tm0 = fmaxf(tm0, fmaxf(sf[j][0], sf[j][1]));
            tm1 = fmaxf(tm1, fmaxf(sf[j][2], sf[j][3]));
        }
        tm0 = fmaxf(tm0, __shfl_xor_sync(0xffffffffu, tm0, 1));
        tm0 = fmaxf(tm0, __shfl_xor_sync(0xffffffffu, tm0, 2));
        tm1 = fmaxf(tm1, __shfl_xor_sync(0xffffffffu, tm1, 1));
        tm1 = fmaxf(tm1, __shfl_xor_sync(0xffffffffu, tm1, 2));
        float nm0 = fmaxf(m0, tm0), nm1 = fmaxf(m1, tm1);
        float cc0 = __expf(m0 - nm0), cc1 = __expf(m1 - nm1);
        l0 *= cc0; l1 *= cc1;
        #pragma unroll
        for (int j = 0; j < 8; j++) {
            oa[j][0] *= cc0; oa[j][1] *= cc0;
            oa[j][2] *= cc1; oa[j][3] *= cc1;
        }
        float ps0 = 0.f, ps1 = 0.f;
        #pragma unroll
        for (int j = 0; j < 8; j++) {
            sf[j][0] = __expf(sf[j][0] - nm0);
            sf[j][1] = __expf(sf[j][1] - nm0);
            sf[j][2] = __expf(sf[j][2] - nm1);
            sf[j][3] = __expf(sf[j][3] - nm1);
            ps0 += sf[j][0] + sf[j][1];
            ps1 += sf[j][2] + sf[j][3];
        }
        l0 += ps0; l1 += ps1; m0 = nm0; m1 = nm1;

        unsigned pf[4][4];
        #pragma unroll
        for (int t2 = 0; t2 < 4; t2++) {
            pf[t2][0] = pack_bf16(sf[2*t2][0],   sf[2*t2][1]);
            pf[t2][1] = pack_bf16(sf[2*t2][2],   sf[2*t2][3]);
            pf[t2][2] = pack_bf16(sf[2*t2+1][0], sf[2*t2+1][1]);
            pf[t2][3] = pack_bf16(sf[2*t2+1][2], sf[2*t2+1][3]);
        }
        #pragma unroll
        for (int t2 = 0; t2 < 4; t2++) {
            #pragma unroll
            for (int g = 0; g < 4; g++) {
                unsigned bv[4];
                ldsm_x4_t(bv, smem_u32(&VsB[(16*t2 + l15)*ATS + 16*g + lH8]));
                mma_bf16(oa[2*g+0], pf[t2], bv[0], bv[1]);
                mma_bf16(oa[2*g+1], pf[t2], bv[2], bv[3]);
            }
        }
        __syncthreads();
    }

    l0 += __shfl_xor_sync(0xffffffffu, l0, 1);
    l0 += __shfl_xor_sync(0xffffffffu, l0, 2);
    l1 += __shfl_xor_sync(0xffffffffu, l1, 1);
    l1 += __shfl_xor_sync(0xffffffffu, l1, 2);
    float inv0 = 1.f / l0, inv1 = 1.f / l1;

    bf16* c0p = ctx + (size_t)(b*SS + rowg0)*DDIM + h*DH + c2;
    bf16* c1p = ctx + (size_t)(b*SS + rowg1)*DDIM + h*DH + c2;
    #pragma unroll
    for (int j = 0; j < 8; j++) {
        *(bf162*)(c0p + 8*j) = __floats2bfloat162_rn(oa[j][0]*inv0, oa[j][1]*inv0);
        *(bf162*)(c1p + 8*j) = __floats2bfloat162_rn(oa[j][2]*inv1, oa[j][3]*inv1);
    }
}

// ---------------- gate ----------------
__global__ void zero_cnt_kernel(int* cnt) {
    if (threadIdx.x < EE) cnt[threadIdx.x] = 0;
}

__global__ void gate_kernel(const float* __restrict__ h, const float* __restrict__ gw,
                            const float* __restrict__ gb, float* __restrict__ sc,
                            int* __restrict__ cnt, int* __restrict__ list)
{
    int warp = (blockIdx.x * blockDim.x + threadIdx.x) >> 5;
    if (warp >= NTOK) return;
    int lane = threadIdx.x & 31;
    float a[8] = {0,0,0,0,0,0,0,0};
    const float* hr = h + (size_t)warp * DDIM;
    for (int d = lane; d < DDIM; d += 32) {
        float hv = hr[d];
        float4 w0 = *(const float4*)(gw + (size_t)d*EE);
        float4 w1 = *(const float4*)(gw + (size_t)d*EE + 4);
        a[0]+=hv*w0.x; a[1]+=hv*w0.y; a[2]+=hv*w0.z; a[3]+=hv*w0.w;
        a[4]+=hv*w1.x; a[5]+=hv*w1.y; a[6]+=hv*w1.z; a[7]+=hv*w1.w;
    }
    #pragma unroll
    for (int e = 0; e < 8; e++)
        #pragma unroll
        for (int o = 16; o > 0; o >>= 1)
            a[e] += __shfl_down_sync(0xffffffffu, a[e], o);
    if (lane == 0) {
        float lg[8];
        #pragma unroll
        for (int e = 0; e < 8; e++) lg[e] = a[e] + gb[e];
        int i0 = 0; float v0 = lg[0];
        #pragma unroll
        for (int e = 1; e < 8; e++) if (lg[e] > v0) { v0 = lg[e]; i0 = e; }
        int i1 = -1; float v1 = -3.0e38f;
        #pragma unroll
        for (int e = 0; e < 8; e++) if (e != i0 && lg[e] > v1) { v1 = lg[e]; i1 = e; }
        float e1 = __expf(v1 - v0);
        float s0 = 1.f / (1.f + e1);
        float s1 = e1 * s0;
        sc[2*warp]   = s0;
        sc[2*warp+1] = s1;
        int p0 = atomicAdd(&cnt[i0], 1);
        list[(size_t)i0*CAP + p0] = 2*warp;
        int p1 = atomicAdd(&cnt[i1], 1);
        list[(size_t)i1*CAP + p1] = 2*warp + 1;
    }
}

// ---------------- combine: warp-per-row ----------------
__global__ void combine_kernel(const float* __restrict__ h, const float* __restrict__ o2,
                               const float* __restrict__ sc, const float* __restrict__ xa,
                               const float* __restrict__ g, const float* __restrict__ b,
                               float* __restrict__ out)
{
    int wid = threadIdx.x >> 5, lane = threadIdx.x & 31;
    int t = blockIdx.x * 8 + wid;
    const float* hr = h + (size_t)t*DDIM;
    const float* r0 = o2 + (size_t)(2*t)*DDIM;
    const float* r1 = o2 + (size_t)(2*t+1)*DDIM;
    float s0 = sc[2*t], s1 = sc[2*t+1];

    float4 tv[6];
    float s = 0.f;
    #pragma unroll
    for (int j = 0; j < 6; j++) {
        int d = lane*4 + j*128;
        float4 hv = *(const float4*)(hr + d);
        float4 a0 = *(const float4*)(r0 + d);
        float4 a1 = *(const float4*)(r1 + d);
        tv[j].x = hv.x + s0*a0.x + s1*a1.x;
        tv[j].y = hv.y + s0*a0.y + s1*a1.y;
        tv[j].z = hv.z + s0*a0.z + s1*a1.z;
        tv[j].w = hv.w + s0*a0.w + s1*a1.w;
        s += (tv[j].x + tv[j].y) + (tv[j].z + tv[j].w);
    }
    #pragma unroll
    for (int o = 16; o > 0; o >>= 1) s += __shfl_xor_sync(0xffffffffu, s, o);
    float mean = s * (1.f / DDIM);

    float vs = 0.f;
    #pragma unroll
    for (int j = 0; j < 6; j++) {
        float a0 = tv[j].x - mean, a1 = tv[j].y - mean;
        float a2 = tv[j].z - mean, a3 = tv[j].w - mean;
        vs += (a0*a0 + a1*a1) + (a2*a2 + a3*a3);
    }
    #pragma unroll
    for (int o = 16; o > 0; o >>= 1) vs += __shfl_xor_sync(0xffffffffu, vs, o);
    float rstd = rsqrtf(vs * (1.f / DDIM) + 1e-5f);

    #pragma unroll
    for (int j = 0; j < 6; j++) {
        int d = lane*4 + j*128;
        float4 gg = *(const float4*)(g + d);
        float4 bb = *(const float4*)(b + d);
        float4 xv = *(const float4*)(xa + (size_t)t*DDIM + d);
        float4 o;
        o.x = xv.x + (tv[j].x - mean)*rstd*gg.x + bb.x;
        o.y = xv.y + (tv[j].y - mean)*rstd*gg.y + bb.y;
        o.z = xv.z + (tv[j].z - mean)*rstd*gg.z + bb.z;
        o.w = xv.w + (tv[j].w - mean)*rstd*gg.w + bb.w;
        *(float4*)(out + (size_t)t*DDIM + d) = o;
    }
}

// ---------------- launch ----------------
extern "C" void kernel_launch(void* const* d_in, const int* in_sizes, int n_in,
                              void* d_out, int out_size)
{
    const float* x        = (const float*)d_in[0];
    const float* ln_a_g   = (const float*)d_in[2];
    const float* ln_a_b   = (const float*)d_in[3];
    const float* wq       = (const float*)d_in[4];
    const float* bq       = (const float*)d_in[5];
    const float* wk       = (const float*)d_in[6];
    const float* bk       = (const float*)d_in[7];
    const float* wv       = (const float*)d_in[8];
    const float* bv       = (const float*)d_in[9];
    const float* wo       = (const float*)d_in[10];
    const float* bo       = (const float*)d_in[11];
    const float* ln_f_g   = (const float*)d_in[12];
    const float* ln_f_b   = (const float*)d_in[13];
    const float* gate_w   = (const float*)d_in[14];
    const float* gate_b   = (const float*)d_in[15];
    const float* w1       = (const float*)d_in[16];
    const float* b1       = (const float*)d_in[17];
    const float* w2       = (const float*)d_in[18];
    const float* b2       = (const float*)d_in[19];
    const float* moe_g    = (const float*)d_in[20];
    const float* moe_b    = (const float*)d_in[21];
    float* out = (float*)d_out;

    bf16 *a, *qb, *kb, *vb, *ctx, *hrb, *y1, *bwq, *bwk, *bwv, *bwo, *bw1, *bw2;
    float *xa, *h, *o2, *sc;
    int *cnt, *list;
    cudaGetSymbolAddress((void**)&a,   g_a);
    cudaGetSymbolAddress((void**)&qb,  g_q);
    cudaGetSymbolAddress((void**)&kb,  g_k);
    cudaGetSymbolAddress((void**)&vb,  g_v);
    cudaGetSymbolAddress((void**)&ctx, g_ctx);
    cudaGetSymbolAddress((void**)&xa,  g_xa);
    cudaGetSymbolAddress((void**)&h,   g_h);
    cudaGetSymbolAddress((void**)&hrb, g_hr);
    cudaGetSymbolAddress((void**)&y1,  g_y1);
    cudaGetSymbolAddress((void**)&o2,  g_o2);
    cudaGetSymbolAddress((void**)&sc,  g_sc);
    cudaGetSymbolAddress((void**)&cnt, g_cnt);
    cudaGetSymbolAddress((void**)&list,g_list);
    cudaGetSymbolAddress((void**)&bwq, g_bwq);
    cudaGetSymbolAddress((void**)&bwk, g_bwk);
    cudaGetSymbolAddress((void**)&bwv, g_bwv);
    cudaGetSymbolAddress((void**)&bwo, g_bwo);
    cudaGetSymbolAddress((void**)&bw1, g_bw1);
    cudaGetSymbolAddress((void**)&bw2, g_bw2);

    cudaFuncSetAttribute(bgemm_k<false,false,false,false,true,true>,
                         cudaFuncAttributeMaxDynamicSharedMemorySize, GSMEM);
    cudaFuncSetAttribute(bgemm_k<false,false,false,true,false,false>,
                         cudaFuncAttributeMaxDynamicSharedMemorySize, GSMEM);
    cudaFuncSetAttribute(bgemm_k<true,false,true,false,true,false>,
                         cudaFuncAttributeMaxDynamicSharedMemorySize, GSMEM);
    cudaFuncSetAttribute(bgemm_k<true,true,false,false,false,false>,
                         cudaFuncAttributeMaxDynamicSharedMemorySize, GSMEM);

    // side stream + events (created once at the uncaptured correctness call)
    static cudaStream_t sW = nullptr;
    static cudaEvent_t evFork = nullptr, evQKVW = nullptr, evFFW = nullptr;
    if (sW == nullptr) {
        cudaStreamCreateWithFlags(&sW, cudaStreamNonBlocking);
        cudaEventCreateWithFlags(&evFork,  cudaEventDisableTiming);
        cudaEventCreateWithFlags(&evQKVW, cudaEventDisableTiming);
        cudaEventCreateWithFlags(&evFFW,  cudaEventDisableTiming);
    }

    // ---- fork: weight conversions on side stream ----
    cudaEventRecord(evFork, 0);
    cudaStreamWaitEvent(sW, evFork, 0);
    {
        int nqkv4 = DDIM*DDIM/4;
        conv4_bf16_kernel<<<dim3((nqkv4 + 255)/256, 1, 4), 256, 0, sW>>>(
            wq, wk, wv, wo, bwq, bwk, bwv, bwo, nqkv4);
        cudaEventRecord(evQKVW, sW);
        int nff4 = EE*DDIM*HID/4;
        int gf = (nff4 + 1023)/1024;
        conv_bf16_ilp_kernel<<<gf, 256, 0, sW>>>(w1, bw1, nff4);
        conv_bf16_ilp_kernel<<<gf, 256, 0, sW>>>(w2, bw2, nff4);
        cudaEventRecord(evFFW, sW);
    }

    // 1) a = bf16(ln_attn(x))  — concurrent with conversions
    ln_kernel<1><<<NTOK/8, 256>>>(x, ln_a_g, ln_a_b, nullptr, a);

    // join: QKV needs bwq/bwk/bwv
    cudaStreamWaitEvent(0, evQKVW, 0);

    // 2) fused q,k,v projections -> bf16 outputs
    dim3 gQKV(DDIM/128, NTOK/128, 3);
    bgemm_k<false,false,false,false,true,true><<<gQKV, 256, GSMEM>>>(
        NTOK, DDIM, DDIM, a, DDIM, bwq, bq, nullptr, (float*)qb, DDIM, nullptr, nullptr,
        bwk, bk, (float*)kb, bwv, bv, (float*)vb);

    // 3) tensor-core flash attention (causal), ctx bf16
    attn_tc_kernel<<<dim3(SS/64, HH, BB), 128>>>(qb, kb, vb, ctx);

    // 4) xa = x + ctx @ wo + bo
    dim3 gO(DDIM/128, NTOK/128, 1);
    bgemm_k<false,false,false,true,false,false><<<gO, 256, GSMEM>>>(
        NTOK, DDIM, DDIM, ctx, DDIM, bwo, bo, x, xa, DDIM, nullptr, nullptr,
        nullptr, nullptr, nullptr, nullptr, nullptr, nullptr);

    // 5) h = ln_ff(xa) (f32) + hr (bf16)
    ln_kernel<2><<<NTOK/8, 256>>>(xa, ln_f_g, ln_f_b, h, hrb);

    // 6) gate: top-2 per token + per-expert pair lists
    zero_cnt_kernel<<<1, 32>>>(cnt);
    gate_kernel<<<NTOK/8, 256>>>(h, gate_w, gate_b, sc, cnt, list);

    // join: expert GEMMs need bw1/bw2
    cudaStreamWaitEvent(0, evFFW, 0);

    // 7) expert GEMM1: y1[pair] = bf16(relu(hr[token] @ w1[e] + b1[e]))
    bgemm_k<true,false,true,false,true,false><<<dim3(HID/128, CAP/128, EE), 256, GSMEM>>>(
        CAP, HID, DDIM, hrb, DDIM, bw1, b1, nullptr, (float*)y1, HID, list, cnt,
        nullptr, nullptr, nullptr, nullptr, nullptr, nullptr);

    // 8) expert GEMM2: o2[pair] = y1[pair] @ w2[e] + b2[e]
    bgemm_k<true,true,false,false,false,false><<<dim3(DDIM/128, CAP/128, EE), 256, GSMEM>>>(
        CAP, DDIM, HID, y1, HID, bw2, b2, nullptr, o2, DDIM, list, cnt,
        nullptr, nullptr, nullptr, nullptr, nullptr, nullptr);

    // 9) combine + post-LN + final residual
    combine_kernel<<<NTOK/8, 256>>>(h, o2, sc, xa, moe_g, moe_b, out);
}